// round 6
// baseline (speedup 1.0000x reference)
#include <cuda_runtime.h>
#include <cstdint>

#define NN 100000
#define NE 1600000
#define C 128
#define C3 384
#define NLAYERS 3
#define SCAN_B 512
#define SCAN_NB ((NN + SCAN_B - 1) / SCAN_B)   // 196

// ---------------- scratch (device globals; no allocation allowed) ----------------
__device__ __align__(256) float g_h[NN * C];        // hidden state
__device__ __align__(256) float g_m[NN * C];        // per-layer message h@W
__device__ __align__(256) float g_agg[NN * C];      // aggregated messages
__device__ __align__(256) float g_gi[NN * C3];      // GRU input gates
__device__ __align__(256) float g_gh[NN * C3];      // GRU hidden gates
__device__ __align__(256) float g_wihT[C * C3];     // w_ih^T -> [K=128, 384]
__device__ __align__(256) float g_whhT[C * C3];
// CSR build
__device__ __align__(256) int g_deg[NN];
__device__ __align__(256) int g_bsum[SCAN_NB];
__device__ __align__(256) int g_rowptr[NN + 1];
__device__ __align__(256) int g_cur[NN];
__device__ __align__(256) int g_srclist[NE];
__device__ int g_is64;   // edge_index dtype flag (1 = int64, 0 = int32)

// ---------------- dtype detection ----------------
// int64 edge values < 100000 (non-negative) -> every odd 32-bit word is 0.
// int32 random values in [0,100000) -> odd words are ~never all zero.
__global__ void detect_kernel(const unsigned int* __restrict__ ei32) {
    if (blockIdx.x == 0 && threadIdx.x == 0) {
        int is64 = 1;
        for (int i = 1; i < 64; i += 2)
            if (ei32[i] != 0u) { is64 = 0; break; }
        g_is64 = is64;
    }
}

__device__ __forceinline__ int load_edge(const void* ei, long long idx) {
    int v;
    if (g_is64) v = (int)((const long long*)ei)[idx];
    else        v = ((const int*)ei)[idx];
    return min(max(v, 0), NN - 1);
}

// ---------------- init / CSR build ----------------
__global__ void init_h_kernel(const float* __restrict__ x) {
    int i = blockIdx.x * blockDim.x + threadIdx.x;
    if (i < NN * C) g_h[i] = x[i];
}

__global__ void zero_deg_kernel() {
    int i = blockIdx.x * blockDim.x + threadIdx.x;
    if (i < NN) g_deg[i] = 0;
}

__global__ void count_kernel(const void* __restrict__ ei) {
    int e = blockIdx.x * blockDim.x + threadIdx.x;
    if (e < NE) {
        int dst = load_edge(ei, (long long)NE + e);
        atomicAdd(&g_deg[dst], 1);
    }
}

// hierarchical exclusive scan of g_deg -> g_rowptr
__global__ void scanA_kernel() {   // per-block sums
    __shared__ int sh[SCAN_B];
    int i = blockIdx.x * SCAN_B + threadIdx.x;
    sh[threadIdx.x] = (i < NN) ? g_deg[i] : 0;
    __syncthreads();
    for (int off = SCAN_B / 2; off > 0; off >>= 1) {
        if (threadIdx.x < off) sh[threadIdx.x] += sh[threadIdx.x + off];
        __syncthreads();
    }
    if (threadIdx.x == 0) g_bsum[blockIdx.x] = sh[0];
}

__global__ void scanB_kernel() {   // serial exclusive scan of 196 block sums
    if (threadIdx.x == 0 && blockIdx.x == 0) {
        int run = 0;
        for (int b = 0; b < SCAN_NB; b++) {
            int v = g_bsum[b];
            g_bsum[b] = run;
            run += v;
        }
    }
}

__global__ void scanC_kernel() {   // local exclusive scan + block offset
    __shared__ int sh[SCAN_B];
    int i = blockIdx.x * SCAN_B + threadIdx.x;
    int v = (i < NN) ? g_deg[i] : 0;
    sh[threadIdx.x] = v;
    __syncthreads();
    for (int off = 1; off < SCAN_B; off <<= 1) {
        int t = (threadIdx.x >= off) ? sh[threadIdx.x - off] : 0;
        __syncthreads();
        sh[threadIdx.x] += t;
        __syncthreads();
    }
    if (i < NN) {
        int excl = sh[threadIdx.x] - v + g_bsum[blockIdx.x];
        g_rowptr[i] = excl;
        g_cur[i] = excl;
    }
    if (i == NN - 1) g_rowptr[NN] = NE;
}

__global__ void fill_kernel(const void* __restrict__ ei) {
    int e = blockIdx.x * blockDim.x + threadIdx.x;
    if (e < NE) {
        int src = load_edge(ei, e);
        int dst = load_edge(ei, (long long)NE + e);
        int pos = atomicAdd(&g_cur[dst], 1);
        if (pos >= 0 && pos < NE) g_srclist[pos] = src;
    }
}

__global__ void transpose_w_kernel(const float* __restrict__ w_ih,
                                   const float* __restrict__ w_hh) {
    int idx = blockIdx.x * blockDim.x + threadIdx.x;  // over C3*C
    if (idx < C3 * C) {
        int j = idx / C;   // w row (0..383)
        int k = idx % C;   // w col (0..127)
        g_wihT[k * C3 + j] = w_ih[j * C + k];
        g_whhT[k * C3 + j] = w_hh[j * C + k];
    }
}

// ---------------- gather aggregation: one warp per node, mean over in-edges ----------------
__global__ void gather_kernel() {
    int warp = (blockIdx.x * blockDim.x + threadIdx.x) >> 5;
    int lane = threadIdx.x & 31;
    if (warp >= NN) return;
    int s = g_rowptr[warp];
    int e = g_rowptr[warp + 1];
    float4 acc = make_float4(0.f, 0.f, 0.f, 0.f);
    int i = s;
    for (; i + 2 <= e; i += 2) {
        int s0 = g_srclist[i];
        int s1 = g_srclist[i + 1];
        float4 v0 = *(const float4*)(g_m + (size_t)s0 * C + lane * 4);
        float4 v1 = *(const float4*)(g_m + (size_t)s1 * C + lane * 4);
        acc.x += v0.x + v1.x;  acc.y += v0.y + v1.y;
        acc.z += v0.z + v1.z;  acc.w += v0.w + v1.w;
    }
    if (i < e) {
        int s0 = g_srclist[i];
        float4 v0 = *(const float4*)(g_m + (size_t)s0 * C + lane * 4);
        acc.x += v0.x;  acc.y += v0.y;  acc.z += v0.z;  acc.w += v0.w;
    }
    float sc = 1.0f / fmaxf((float)(e - s), 1.0f);
    acc.x *= sc;  acc.y *= sc;  acc.z *= sc;  acc.w *= sc;
    *(float4*)(g_agg + (size_t)warp * C + lane * 4) = acc;
}

// ---------------- fp32 GEMM with packed f32x2 FMAs ----------------
// MODE 0: g_m  = g_h   @ Bext(weight[l])          [N=128]
// MODE 1: g_gi = g_agg @ g_wihT + b_ih            [N=384]
// MODE 2: g_gh = g_h   @ g_whhT + b_hh            [N=384]
// Block tile 128x128, 256 threads, 8x8 micro-tile, BK=8, A duplicated in smem.
template <int MODE>
__global__ void __launch_bounds__(256)
gemm_kernel(const float* __restrict__ Bext, const float* __restrict__ bias)
{
    constexpr int N = (MODE == 0) ? 128 : 384;
    const float* __restrict__ A = (MODE == 1) ? g_agg : g_h;
    const float* __restrict__ B = (MODE == 0) ? Bext : (MODE == 1 ? g_wihT : g_whhT);
    float* __restrict__ Cout    = (MODE == 0) ? g_m  : (MODE == 1 ? g_gi  : g_gh);

    __shared__ __align__(16) float As2[8][256];  // [k][2*m] duplicated
    __shared__ __align__(16) float Bs[8][128];

    int tid = threadIdx.x;
    int tx = tid & 15;   // N direction
    int ty = tid >> 4;   // M direction
    int rowBase = blockIdx.y * 128;
    int colBase = blockIdx.x * 128;

    int a_row = tid >> 1;          // 0..127
    int a_col = (tid & 1) * 4;     // 0 or 4
    int b_row = tid >> 5;          // 0..7
    int b_col = (tid & 31) * 4;    // 0..124

    unsigned long long acc[8][4];
#pragma unroll
    for (int i = 0; i < 8; i++)
#pragma unroll
        for (int j = 0; j < 4; j++) acc[i][j] = 0ULL;

    for (int k0 = 0; k0 < 128; k0 += 8) {
        int gr = rowBase + a_row;
        float4 av;
        if (gr < NN) av = *(const float4*)(A + (size_t)gr * C + (k0 + a_col));
        else         av = make_float4(0.f, 0.f, 0.f, 0.f);
        As2[a_col + 0][2 * a_row] = av.x;  As2[a_col + 0][2 * a_row + 1] = av.x;
        As2[a_col + 1][2 * a_row] = av.y;  As2[a_col + 1][2 * a_row + 1] = av.y;
        As2[a_col + 2][2 * a_row] = av.z;  As2[a_col + 2][2 * a_row + 1] = av.z;
        As2[a_col + 3][2 * a_row] = av.w;  As2[a_col + 3][2 * a_row + 1] = av.w;

        float4 bv = *(const float4*)(B + (size_t)(k0 + b_row) * N + colBase + b_col);
        *(float4*)&Bs[b_row][b_col] = bv;

        __syncthreads();

#pragma unroll
        for (int k = 0; k < 8; k++) {
            unsigned long long a2[8], b2[4];
#pragma unroll
            for (int i = 0; i < 4; i++) {
                a2[i]     = *(const unsigned long long*)&As2[k][(ty * 4 + i) * 2];
                a2[i + 4] = *(const unsigned long long*)&As2[k][(64 + ty * 4 + i) * 2];
            }
            b2[0] = *(const unsigned long long*)&Bs[k][tx * 4];
            b2[1] = *(const unsigned long long*)&Bs[k][tx * 4 + 2];
            b2[2] = *(const unsigned long long*)&Bs[k][64 + tx * 4];
            b2[3] = *(const unsigned long long*)&Bs[k][64 + tx * 4 + 2];
#pragma unroll
            for (int i = 0; i < 8; i++)
#pragma unroll
                for (int j = 0; j < 4; j++)
                    asm("fma.rn.f32x2 %0, %1, %2, %3;"
                        : "=l"(acc[i][j])
                        : "l"(a2[i]), "l"(b2[j]), "l"(acc[i][j]));
        }
        __syncthreads();
    }

#pragma unroll
    for (int i = 0; i < 8; i++) {
        int r = rowBase + (i < 4 ? ty * 4 + i : 64 + ty * 4 + (i - 4));
        if (r < NN) {
#pragma unroll
            for (int j = 0; j < 4; j++) {
                int cb = colBase + (j < 2 ? tx * 4 + j * 2 : 64 + tx * 4 + (j - 2) * 2);
                float2 v = *reinterpret_cast<float2*>(&acc[i][j]);
                float o0 = v.x;
                float o1 = v.y;
                if (MODE != 0) { o0 += bias[cb]; o1 += bias[cb + 1]; }
                *(float2*)&Cout[(size_t)r * N + cb] = make_float2(o0, o1);
            }
        }
    }
}

// ---------------- GRU gates (elementwise) ----------------
__global__ void gate_kernel() {
    int idx = blockIdx.x * blockDim.x + threadIdx.x;
    if (idx < NN * C) {
        int n = idx >> 7;
        int c = idx & 127;
        size_t b = (size_t)n * C3;
        float ir = g_gi[b + c], iz = g_gi[b + C + c], in_ = g_gi[b + 2 * C + c];
        float hr = g_gh[b + c], hz = g_gh[b + C + c], hn  = g_gh[b + 2 * C + c];
        float r  = 1.0f / (1.0f + __expf(-(ir + hr)));
        float z  = 1.0f / (1.0f + __expf(-(iz + hz)));
        float nv = tanhf(in_ + r * hn);
        float h  = g_h[idx];
        g_h[idx] = (1.0f - z) * nv + z * h;
    }
}

// ---------------- final mean + tanh ----------------
__global__ void mean_tanh_kernel(float* __restrict__ out) {
    int gtid = blockIdx.x * blockDim.x + threadIdx.x;
    int node = gtid >> 5;
    int lane = threadIdx.x & 31;
    if (node < NN) {
        float4 v = *(const float4*)(g_h + (size_t)node * C + lane * 4);
        float s = v.x + v.y + v.z + v.w;
#pragma unroll
        for (int o = 16; o > 0; o >>= 1) s += __shfl_down_sync(0xffffffffu, s, o);
        if (lane == 0) out[node] = tanhf(s * (1.0f / 128.0f));
    }
}

// ---------------- launch ----------------
extern "C" void kernel_launch(void* const* d_in, const int* in_sizes, int n_in,
                              void* d_out, int out_size) {
    // positional defaults (metadata order: x, edge_index, weight, w_ih, w_hh, b_ih, b_hh)
    int ix = 0, ie = 1, iw = 2, iwih = 3, iwhh = 4, ibih = 5, ibhh = 6;
    // size-based override (robust to reordering; preserves relative order of ties)
    {
        int w_seen = 0, b_seen = 0;
        for (int i = 0; i < n_in; i++) {
            long long s = in_sizes[i];
            if (s == (long long)NN * C) ix = i;
            else if (s == 2LL * NE) ie = i;
            else if (s == (long long)C3 * C) {
                if (w_seen == 0) iw = i;
                else if (w_seen == 1) iwih = i;
                else if (w_seen == 2) iwhh = i;
                w_seen++;
            } else if (s == C3) {
                if (b_seen == 0) ibih = i;
                else if (b_seen == 1) ibhh = i;
                b_seen++;
            }
        }
    }
    const float* x      = (const float*)d_in[ix];
    const void*  ei     = d_in[ie];
    const float* weight = (const float*)d_in[iw];    // [3,128,128]
    const float* w_ih   = (const float*)d_in[iwih];  // [384,128]
    const float* w_hh   = (const float*)d_in[iwhh];
    const float* b_ih   = (const float*)d_in[ibih];
    const float* b_hh   = (const float*)d_in[ibhh];
    float*       out    = (float*)d_out;

    const int NC = NN * C;
    detect_kernel<<<1, 32>>>((const unsigned int*)ei);
    init_h_kernel<<<(NC + 255) / 256, 256>>>(x);
    zero_deg_kernel<<<(NN + 255) / 256, 256>>>();
    count_kernel<<<(NE + 255) / 256, 256>>>(ei);
    scanA_kernel<<<SCAN_NB, SCAN_B>>>();
    scanB_kernel<<<1, 32>>>();
    scanC_kernel<<<SCAN_NB, SCAN_B>>>();
    fill_kernel<<<(NE + 255) / 256, 256>>>(ei);
    transpose_w_kernel<<<(C3 * C + 255) / 256, 256>>>(w_ih, w_hh);

    dim3 grid1(1, (NN + 127) / 128);   // Nout = 128
    dim3 grid3(3, (NN + 127) / 128);   // Nout = 384
    int gather_blocks = (NN * 32 + 255) / 256;

    for (int l = 0; l < NLAYERS; l++) {
        gemm_kernel<0><<<grid1, 256>>>(weight + (size_t)l * C * C, nullptr);
        gather_kernel<<<gather_blocks, 256>>>();
        gemm_kernel<1><<<grid3, 256>>>(nullptr, b_ih);
        gemm_kernel<2><<<grid3, 256>>>(nullptr, b_hh);
        gate_kernel<<<(NC + 255) / 256, 256>>>();
    }

    mean_tanh_kernel<<<(NN * 32 + 255) / 256, 256>>>(out);
}

// round 8
// speedup vs baseline: 1.0313x; 1.0313x over previous
#include <cuda_runtime.h>
#include <cuda_bf16.h>
#include <cstdint>

#define NN 100000
#define NE 1600000
#define C 128
#define C3 384
#define NLAYERS 3
#define SCAN_B 512
#define SCAN_NB ((NN + SCAN_B - 1) / SCAN_B)   // 196

// padded tile layout: [128 rows][68 uint32 words] (64 used, +4 pad => conflict-free frags)
#define TSTR 68
#define TILE_WORDS (128 * TSTR)       // 8704 uint32
#define TILE_BYTES (TILE_WORDS * 4)   // 34816 B

// ================= scratch (device globals; no allocation allowed) =================
__device__ __align__(256) float g_h[NN * C];
__device__ __align__(256) float g_m[NN * C];
__device__ __align__(256) float g_agg[NN * C];
__device__ __align__(256) float g_gi[NN * C3];
__device__ __align__(256) float g_gh[NN * C3];
// pre-split padded B tiles: 0-2 = W_l (as [n][k]), 3-5 = w_ih blocks, 6-8 = w_hh blocks
__device__ __align__(256) uint32_t g_btile_hi[9 * TILE_WORDS];
__device__ __align__(256) uint32_t g_btile_lo[9 * TILE_WORDS];
// CSR build
__device__ __align__(256) int g_deg[NN];
__device__ __align__(256) int g_bsum[SCAN_NB];
__device__ __align__(256) int g_rowptr[NN + 1];
__device__ __align__(256) int g_cur[NN];
__device__ __align__(256) int g_srclist[NE];
__device__ int g_is64;

// ================= dtype detection (edge_index int64 vs int32) =================
__global__ void detect_kernel(const unsigned int* __restrict__ ei32) {
    if (blockIdx.x == 0 && threadIdx.x == 0) {
        int is64 = 1;
        for (int i = 1; i < 64; i += 2)
            if (ei32[i] != 0u) { is64 = 0; break; }
        g_is64 = is64;
    }
}
__device__ __forceinline__ int load_edge(const void* ei, long long idx) {
    int v;
    if (g_is64) v = (int)((const long long*)ei)[idx];
    else        v = ((const int*)ei)[idx];
    return min(max(v, 0), NN - 1);
}

// ================= init / CSR build =================
__global__ void init_h_kernel(const float* __restrict__ x) {
    int i = blockIdx.x * blockDim.x + threadIdx.x;
    if (i < NN * C) g_h[i] = x[i];
}
__global__ void zero_deg_kernel() {
    int i = blockIdx.x * blockDim.x + threadIdx.x;
    if (i < NN) g_deg[i] = 0;
}
__global__ void count_kernel(const void* __restrict__ ei) {
    int e = blockIdx.x * blockDim.x + threadIdx.x;
    if (e < NE) atomicAdd(&g_deg[load_edge(ei, (long long)NE + e)], 1);
}
__global__ void scanA_kernel() {
    __shared__ int sh[SCAN_B];
    int i = blockIdx.x * SCAN_B + threadIdx.x;
    sh[threadIdx.x] = (i < NN) ? g_deg[i] : 0;
    __syncthreads();
    for (int off = SCAN_B / 2; off > 0; off >>= 1) {
        if (threadIdx.x < off) sh[threadIdx.x] += sh[threadIdx.x + off];
        __syncthreads();
    }
    if (threadIdx.x == 0) g_bsum[blockIdx.x] = sh[0];
}
__global__ void scanB_kernel() {
    if (threadIdx.x == 0 && blockIdx.x == 0) {
        int run = 0;
        for (int b = 0; b < SCAN_NB; b++) { int v = g_bsum[b]; g_bsum[b] = run; run += v; }
    }
}
__global__ void scanC_kernel() {
    __shared__ int sh[SCAN_B];
    int i = blockIdx.x * SCAN_B + threadIdx.x;
    int v = (i < NN) ? g_deg[i] : 0;
    sh[threadIdx.x] = v;
    __syncthreads();
    for (int off = 1; off < SCAN_B; off <<= 1) {
        int t = (threadIdx.x >= off) ? sh[threadIdx.x - off] : 0;
        __syncthreads();
        sh[threadIdx.x] += t;
        __syncthreads();
    }
    if (i < NN) {
        int excl = sh[threadIdx.x] - v + g_bsum[blockIdx.x];
        g_rowptr[i] = excl;
        g_cur[i] = excl;
    }
    if (i == NN - 1) g_rowptr[NN] = NE;
}
__global__ void fill_kernel(const void* __restrict__ ei) {
    int e = blockIdx.x * blockDim.x + threadIdx.x;
    if (e < NE) {
        int src = load_edge(ei, e);
        int dst = load_edge(ei, (long long)NE + e);
        int pos = atomicAdd(&g_cur[dst], 1);
        if (pos >= 0 && pos < NE) g_srclist[pos] = src;
    }
}

// ================= weight prep: split-bf16 into padded [n][k2] images =================
__global__ void prep_btiles_kernel(const float* __restrict__ weight,
                                   const float* __restrict__ w_ih,
                                   const float* __restrict__ w_hh) {
    int idx = blockIdx.x * blockDim.x + threadIdx.x;   // over 9 * 128 * 64
    if (idx >= 9 * 128 * 64) return;
    int tile = idx >> 13;           // /8192
    int rem  = idx & 8191;
    int n  = rem >> 6;              // output col (0..127)
    int k2 = rem & 63;              // k pair
    float v0, v1;
    if (tile < 3) {                 // B[n][k] = W_l[k][n]
        v0 = weight[tile * 16384 + (k2 * 2)     * 128 + n];
        v1 = weight[tile * 16384 + (k2 * 2 + 1) * 128 + n];
    } else if (tile < 6) {          // w_ih[j][k], j = blk*128 + n
        const float* r = w_ih + ((size_t)((tile - 3) * 128 + n)) * 128;
        v0 = r[k2 * 2];  v1 = r[k2 * 2 + 1];
    } else {
        const float* r = w_hh + ((size_t)((tile - 6) * 128 + n)) * 128;
        v0 = r[k2 * 2];  v1 = r[k2 * 2 + 1];
    }
    __nv_bfloat162 h, l;
    h.x = __float2bfloat16_rn(v0);
    h.y = __float2bfloat16_rn(v1);
    l.x = __float2bfloat16_rn(v0 - __bfloat162float(h.x));
    l.y = __float2bfloat16_rn(v1 - __bfloat162float(h.y));
    size_t o = (size_t)tile * TILE_WORDS + n * TSTR + k2;
    g_btile_hi[o] = *(uint32_t*)&h;
    g_btile_lo[o] = *(uint32_t*)&l;
}

// ================= mma.sync m16n8k16 bf16 helper =================
__device__ __forceinline__ void mma16816(float* c, const uint32_t* a, const uint32_t* b) {
    asm volatile(
        "mma.sync.aligned.m16n8k16.row.col.f32.bf16.bf16.f32 "
        "{%0,%1,%2,%3}, {%4,%5,%6,%7}, {%8,%9}, {%0,%1,%2,%3};"
        : "+f"(c[0]), "+f"(c[1]), "+f"(c[2]), "+f"(c[3])
        : "r"(a[0]), "r"(a[1]), "r"(a[2]), "r"(a[3]), "r"(b[0]), "r"(b[1]));
}

// ================= tensor-core split-bf16 GEMM =================
// MODE 0: g_m  = g_h   @ W_l          (1 col tile, tile id = layer)
// MODE 1: g_gi = g_agg @ w_ih^T + b   (3 col tiles, tiles 3..5)
// MODE 2: g_gh = g_h   @ w_hh^T + b   (3 col tiles, tiles 6..8)
// smem: AH | AL | BH | BL, each 128x68 uint32 (34816 B) -> 139264 B dynamic
#define SMEMSZ (4 * TILE_BYTES)

template <int MODE>
__global__ void __launch_bounds__(256, 1)
mma_gemm_kernel(int layer, const float* __restrict__ bias)
{
    extern __shared__ uint32_t sm[];
    uint32_t* AH = sm;
    uint32_t* AL = sm + TILE_WORDS;
    uint32_t* BH = sm + 2 * TILE_WORDS;
    uint32_t* BL = sm + 3 * TILE_WORDS;

    int tid = threadIdx.x;
    int rowBase = blockIdx.y * 128;
    int colBase = blockIdx.x * 128;
    constexpr int NSTR = (MODE == 0) ? 128 : 384;
    int tileId = (MODE == 0) ? layer : ((MODE == 1) ? 3 : 6) + blockIdx.x;

    // ---- A tile: load f32, split hi/lo bf16 into padded layout ----
    const float* __restrict__ A = (MODE == 1) ? g_agg : g_h;
    for (int i = tid; i < 128 * 32; i += 256) {
        int row = i >> 5;
        int k2  = (i & 31) * 2;          // word index (2 words per float4)
        float4 v = make_float4(0.f, 0.f, 0.f, 0.f);
        int gr = rowBase + row;
        if (gr < NN) v = *(const float4*)(A + (size_t)gr * C + k2 * 2);
        __nv_bfloat162 h0, h1, l0, l1;
        h0.x = __float2bfloat16_rn(v.x);  h0.y = __float2bfloat16_rn(v.y);
        h1.x = __float2bfloat16_rn(v.z);  h1.y = __float2bfloat16_rn(v.w);
        l0.x = __float2bfloat16_rn(v.x - __bfloat162float(h0.x));
        l0.y = __float2bfloat16_rn(v.y - __bfloat162float(h0.y));
        l1.x = __float2bfloat16_rn(v.z - __bfloat162float(h1.x));
        l1.y = __float2bfloat16_rn(v.w - __bfloat162float(h1.y));
        int o = row * TSTR + k2;         // even -> 8B aligned
        *(uint2*)(AH + o) = make_uint2(*(uint32_t*)&h0, *(uint32_t*)&h1);
        *(uint2*)(AL + o) = make_uint2(*(uint32_t*)&l0, *(uint32_t*)&l1);
    }
    // ---- B tile: raw image copy (already padded+split) ----
    {
        const float4* sh = (const float4*)(g_btile_hi + (size_t)tileId * TILE_WORDS);
        const float4* sl = (const float4*)(g_btile_lo + (size_t)tileId * TILE_WORDS);
        float4* dh = (float4*)BH;
        float4* dl = (float4*)BL;
        for (int i = tid; i < TILE_WORDS / 4; i += 256) { dh[i] = sh[i]; dl[i] = sl[i]; }
    }
    __syncthreads();

    // ---- fragments & accumulate: 8 warps as 4(m) x 2(n), warp tile 32x64 ----
    int wid = tid >> 5, lane = tid & 31;
    int gr = lane >> 2, tig = lane & 3;
    int wm = wid >> 1, wn = wid & 1;

    float acc[2][8][4];
#pragma unroll
    for (int mi = 0; mi < 2; mi++)
#pragma unroll
        for (int ni = 0; ni < 8; ni++)
#pragma unroll
            for (int q = 0; q < 4; q++) acc[mi][ni][q] = 0.f;

    const uint32_t* Aps[3] = {AH, AH, AL};
    const uint32_t* Bps[3] = {BH, BL, BH};
#pragma unroll
    for (int p = 0; p < 3; p++) {
        const uint32_t* __restrict__ Ab = Aps[p];
        const uint32_t* __restrict__ Bb = Bps[p];
#pragma unroll
        for (int ks = 0; ks < 8; ks++) {
            uint32_t a[2][4];
#pragma unroll
            for (int mi = 0; mi < 2; mi++) {
                int r0 = wm * 32 + mi * 16 + gr;
                int base = r0 * TSTR + ks * 8 + tig;
                a[mi][0] = Ab[base];
                a[mi][1] = Ab[base + 8 * TSTR];
                a[mi][2] = Ab[base + 4];
                a[mi][3] = Ab[base + 8 * TSTR + 4];
            }
#pragma unroll
            for (int ni = 0; ni < 8; ni++) {
                int n0 = wn * 64 + ni * 8 + gr;
                uint32_t b[2];
                int base = n0 * TSTR + ks * 8 + tig;
                b[0] = Bb[base];
                b[1] = Bb[base + 4];
                mma16816(acc[0][ni], a[0], b);
                mma16816(acc[1][ni], a[1], b);
            }
        }
    }

    // ---- epilogue ----
    float* __restrict__ Cout = (MODE == 0) ? g_m : (MODE == 1) ? g_gi : g_gh;
#pragma unroll
    for (int mi = 0; mi < 2; mi++) {
#pragma unroll
        for (int ni = 0; ni < 8; ni++) {
            int r = rowBase + wm * 32 + mi * 16 + gr;
            int cc = colBase + wn * 64 + ni * 8 + tig * 2;
            float bx = 0.f, by = 0.f;
            if (MODE != 0) { bx = bias[cc]; by = bias[cc + 1]; }
            if (r < NN)
                *(float2*)(Cout + (size_t)r * NSTR + cc) =
                    make_float2(acc[mi][ni][0] + bx, acc[mi][ni][1] + by);
            if (r + 8 < NN)
                *(float2*)(Cout + (size_t)(r + 8) * NSTR + cc) =
                    make_float2(acc[mi][ni][2] + bx, acc[mi][ni][3] + by);
        }
    }
}

// ================= gather aggregation (unchanged, passing) =================
__global__ void gather_kernel() {
    int warp = (blockIdx.x * blockDim.x + threadIdx.x) >> 5;
    int lane = threadIdx.x & 31;
    if (warp >= NN) return;
    int s = g_rowptr[warp];
    int e = g_rowptr[warp + 1];
    float4 acc = make_float4(0.f, 0.f, 0.f, 0.f);
    int i = s;
    for (; i + 2 <= e; i += 2) {
        int s0 = g_srclist[i];
        int s1 = g_srclist[i + 1];
        float4 v0 = *(const float4*)(g_m + (size_t)s0 * C + lane * 4);
        float4 v1 = *(const float4*)(g_m + (size_t)s1 * C + lane * 4);
        acc.x += v0.x + v1.x;  acc.y += v0.y + v1.y;
        acc.z += v0.z + v1.z;  acc.w += v0.w + v1.w;
    }
    if (i < e) {
        int s0 = g_srclist[i];
        float4 v0 = *(const float4*)(g_m + (size_t)s0 * C + lane * 4);
        acc.x += v0.x;  acc.y += v0.y;  acc.z += v0.z;  acc.w += v0.w;
    }
    float sc = 1.0f / fmaxf((float)(e - s), 1.0f);
    acc.x *= sc;  acc.y *= sc;  acc.z *= sc;  acc.w *= sc;
    *(float4*)(g_agg + (size_t)warp * C + lane * 4) = acc;
}

// ================= GRU gates (unchanged) =================
__global__ void gate_kernel() {
    int idx = blockIdx.x * blockDim.x + threadIdx.x;
    if (idx < NN * C) {
        int n = idx >> 7;
        int c = idx & 127;
        size_t b = (size_t)n * C3;
        float ir = g_gi[b + c], iz = g_gi[b + C + c], in_ = g_gi[b + 2 * C + c];
        float hr = g_gh[b + c], hz = g_gh[b + C + c], hn  = g_gh[b + 2 * C + c];
        float r  = 1.0f / (1.0f + __expf(-(ir + hr)));
        float z  = 1.0f / (1.0f + __expf(-(iz + hz)));
        float nv = tanhf(in_ + r * hn);
        float h  = g_h[idx];
        g_h[idx] = (1.0f - z) * nv + z * h;
    }
}

// ================= final mean + tanh (unchanged) =================
__global__ void mean_tanh_kernel(float* __restrict__ out) {
    int gtid = blockIdx.x * blockDim.x + threadIdx.x;
    int node = gtid >> 5;
    int lane = threadIdx.x & 31;
    if (node < NN) {
        float4 v = *(const float4*)(g_h + (size_t)node * C + lane * 4);
        float s = v.x + v.y + v.z + v.w;
#pragma unroll
        for (int o = 16; o > 0; o >>= 1) s += __shfl_down_sync(0xffffffffu, s, o);
        if (lane == 0) out[node] = tanhf(s * (1.0f / 128.0f));
    }
}

// ================= launch =================
extern "C" void kernel_launch(void* const* d_in, const int* in_sizes, int n_in,
                              void* d_out, int out_size) {
    int ix = 0, ie = 1, iw = 2, iwih = 3, iwhh = 4, ibih = 5, ibhh = 6;
    {
        int w_seen = 0, b_seen = 0;
        for (int i = 0; i < n_in; i++) {
            long long s = in_sizes[i];
            if (s == (long long)NN * C) ix = i;
            else if (s == 2LL * NE) ie = i;
            else if (s == (long long)C3 * C) {
                if (w_seen == 0) iw = i;
                else if (w_seen == 1) iwih = i;
                else if (w_seen == 2) iwhh = i;
                w_seen++;
            } else if (s == C3) {
                if (b_seen == 0) ibih = i;
                else if (b_seen == 1) ibhh = i;
                b_seen++;
            }
        }
    }
    const float* x      = (const float*)d_in[ix];
    const void*  ei     = d_in[ie];
    const float* weight = (const float*)d_in[iw];
    const float* w_ih   = (const float*)d_in[iwih];
    const float* w_hh   = (const float*)d_in[iwhh];
    const float* b_ih   = (const float*)d_in[ibih];
    const float* b_hh   = (const float*)d_in[ibhh];
    float*       out    = (float*)d_out;

    static bool attr_set = false;
    if (!attr_set) {
        cudaFuncSetAttribute(mma_gemm_kernel<0>, cudaFuncAttributeMaxDynamicSharedMemorySize, SMEMSZ);
        cudaFuncSetAttribute(mma_gemm_kernel<1>, cudaFuncAttributeMaxDynamicSharedMemorySize, SMEMSZ);
        cudaFuncSetAttribute(mma_gemm_kernel<2>, cudaFuncAttributeMaxDynamicSharedMemorySize, SMEMSZ);
        attr_set = true;
    }

    const int NC = NN * C;
    detect_kernel<<<1, 32>>>((const unsigned int*)ei);
    init_h_kernel<<<(NC + 255) / 256, 256>>>(x);
    zero_deg_kernel<<<(NN + 255) / 256, 256>>>();
    count_kernel<<<(NE + 255) / 256, 256>>>(ei);
    scanA_kernel<<<SCAN_NB, SCAN_B>>>();
    scanB_kernel<<<1, 32>>>();
    scanC_kernel<<<SCAN_NB, SCAN_B>>>();
    fill_kernel<<<(NE + 255) / 256, 256>>>(ei);
    prep_btiles_kernel<<<(9 * 128 * 64 + 255) / 256, 256>>>(weight, w_ih, w_hh);

    const int MT = (NN + 127) / 128;   // 782 row tiles
    dim3 grid1(1, MT), grid3(3, MT);
    int gather_blocks = (NN * 32 + 255) / 256;

    for (int l = 0; l < NLAYERS; l++) {
        mma_gemm_kernel<0><<<grid1, 256, SMEMSZ>>>(l, nullptr);
        gather_kernel<<<gather_blocks, 256>>>();
        mma_gemm_kernel<1><<<grid3, 256, SMEMSZ>>>(0, b_ih);
        mma_gemm_kernel<2><<<grid3, 256, SMEMSZ>>>(0, b_hh);
        gate_kernel<<<(NC + 255) / 256, 256>>>();
    }

    mean_tanh_kernel<<<(NN * 32 + 255) / 256, 256>>>(out);
}

// round 9
// speedup vs baseline: 1.6099x; 1.5610x over previous
#include <cuda_runtime.h>
#include <cuda_bf16.h>
#include <cstdint>

#define NN 100000
#define NE 1600000
#define C 128
#define C3 384
#define NLAYERS 3
#define SCAN_B 512
#define SCAN_NB ((NN + SCAN_B - 1) / SCAN_B)   // 196

// padded tile layouts (uint32 words = bf16x2 pairs), +4 pad words -> conflict-free frags
#define TSTR 68
#define TILE_WORDS (128 * TSTR)       // B tiles: 128 n-rows
#define NROW 64                       // fused-kernel CTA row count
#define A_WORDS (NROW * TSTR)         // A tiles: 64 rows

// ================= scratch (device globals; no allocation allowed) =================
__device__ __align__(256) float g_h[NN * C];        // hidden state (updated in place)
__device__ __align__(256) float g_hbar[NN * C];     // mean-pooled neighbor h
__device__ __align__(256) float g_wfused[3 * 128 * 384];   // W_l @ w_ih^T
// split-bf16 padded B tiles: 0-8 = Wfused (layer,chunk), 9-11 = w_hh chunks
__device__ __align__(256) uint32_t g_btile_hi[12 * TILE_WORDS];
__device__ __align__(256) uint32_t g_btile_lo[12 * TILE_WORDS];
// CSR build
__device__ __align__(256) int g_deg[NN];
__device__ __align__(256) int g_bsum[SCAN_NB];
__device__ __align__(256) int g_rowptr[NN + 1];
__device__ __align__(256) int g_cur[NN];
__device__ __align__(256) int g_srclist[NE];
__device__ int g_is64;

// ================= dtype detection (edge_index int64 vs int32) =================
__global__ void detect_kernel(const unsigned int* __restrict__ ei32) {
    if (blockIdx.x == 0 && threadIdx.x == 0) {
        int is64 = 1;
        for (int i = 1; i < 64; i += 2)
            if (ei32[i] != 0u) { is64 = 0; break; }
        g_is64 = is64;
    }
}
__device__ __forceinline__ int load_edge(const void* ei, long long idx) {
    int v;
    if (g_is64) v = (int)((const long long*)ei)[idx];
    else        v = ((const int*)ei)[idx];
    return min(max(v, 0), NN - 1);
}

// ================= init / CSR build =================
__global__ void init_h_kernel(const float* __restrict__ x) {
    int i = blockIdx.x * blockDim.x + threadIdx.x;
    if (i < NN * C) g_h[i] = x[i];
}
__global__ void zero_deg_kernel() {
    int i = blockIdx.x * blockDim.x + threadIdx.x;
    if (i < NN) g_deg[i] = 0;
}
__global__ void count_kernel(const void* __restrict__ ei) {
    int e = blockIdx.x * blockDim.x + threadIdx.x;
    if (e < NE) atomicAdd(&g_deg[load_edge(ei, (long long)NE + e)], 1);
}
__global__ void scanA_kernel() {
    __shared__ int sh[SCAN_B];
    int i = blockIdx.x * SCAN_B + threadIdx.x;
    sh[threadIdx.x] = (i < NN) ? g_deg[i] : 0;
    __syncthreads();
    for (int off = SCAN_B / 2; off > 0; off >>= 1) {
        if (threadIdx.x < off) sh[threadIdx.x] += sh[threadIdx.x + off];
        __syncthreads();
    }
    if (threadIdx.x == 0) g_bsum[blockIdx.x] = sh[0];
}
__global__ void scanB_kernel() {
    if (threadIdx.x == 0 && blockIdx.x == 0) {
        int run = 0;
        for (int b = 0; b < SCAN_NB; b++) { int v = g_bsum[b]; g_bsum[b] = run; run += v; }
    }
}
__global__ void scanC_kernel() {
    __shared__ int sh[SCAN_B];
    int i = blockIdx.x * SCAN_B + threadIdx.x;
    int v = (i < NN) ? g_deg[i] : 0;
    sh[threadIdx.x] = v;
    __syncthreads();
    for (int off = 1; off < SCAN_B; off <<= 1) {
        int t = (threadIdx.x >= off) ? sh[threadIdx.x - off] : 0;
        __syncthreads();
        sh[threadIdx.x] += t;
        __syncthreads();
    }
    if (i < NN) {
        int excl = sh[threadIdx.x] - v + g_bsum[blockIdx.x];
        g_rowptr[i] = excl;
        g_cur[i] = excl;
    }
    if (i == NN - 1) g_rowptr[NN] = NE;
}
__global__ void fill_kernel(const void* __restrict__ ei) {
    int e = blockIdx.x * blockDim.x + threadIdx.x;
    if (e < NE) {
        int src = load_edge(ei, e);
        int dst = load_edge(ei, (long long)NE + e);
        int pos = atomicAdd(&g_cur[dst], 1);
        if (pos >= 0 && pos < NE) g_srclist[pos] = src;
    }
}

// ================= Wfused = W_l @ w_ih^T (fp32, once) =================
__global__ void wfused_kernel(const float* __restrict__ weight,
                              const float* __restrict__ w_ih) {
    int idx = blockIdx.x * blockDim.x + threadIdx.x;   // l*49152 + k*384 + n
    if (idx >= 3 * 128 * 384) return;
    int l = idx / 49152;
    int rem = idx % 49152;
    int k = rem / 384;
    int n = rem % 384;
    const float* wl = weight + l * 16384 + k * 128;   // W_l[k][:]
    const float* wr = w_ih + (size_t)n * 128;         // w_ih[n][:]
    float s = 0.f;
#pragma unroll 8
    for (int j = 0; j < 128; j++) s += wl[j] * wr[j];
    g_wfused[idx] = s;
}

// ================= B-tile prep: split-bf16 padded images =================
// tiles 0..8: gi, tile = l*3+chunk: B[n][k] = Wfused[l][k][chunk*128+n]
// tiles 9..11: gh, chunk:          B[n][k] = w_hh[chunk*128+n][k]
__global__ void prep_btiles_kernel(const float* __restrict__ w_hh) {
    int idx = blockIdx.x * blockDim.x + threadIdx.x;   // over 12 * 128 * 64
    if (idx >= 12 * 128 * 64) return;
    int tile = idx >> 13;
    int rem  = idx & 8191;
    int n  = rem >> 6;
    int k2 = rem & 63;
    float v0, v1;
    if (tile < 9) {
        int l = tile / 3, chunk = tile % 3;
        const float* base = g_wfused + l * 49152 + chunk * 128 + n;
        v0 = base[(k2 * 2) * 384];
        v1 = base[(k2 * 2 + 1) * 384];
    } else {
        const float* r = w_hh + ((size_t)((tile - 9) * 128 + n)) * 128;
        v0 = r[k2 * 2];  v1 = r[k2 * 2 + 1];
    }
    __nv_bfloat162 h, l2;
    h.x = __float2bfloat16_rn(v0);
    h.y = __float2bfloat16_rn(v1);
    l2.x = __float2bfloat16_rn(v0 - __bfloat162float(h.x));
    l2.y = __float2bfloat16_rn(v1 - __bfloat162float(h.y));
    size_t o = (size_t)tile * TILE_WORDS + n * TSTR + k2;
    g_btile_hi[o] = *(uint32_t*)&h;
    g_btile_lo[o] = *(uint32_t*)&l2;
}

// ================= gather: hbar = mean of h over in-neighbors =================
__global__ void gather_kernel() {
    int warp = (blockIdx.x * blockDim.x + threadIdx.x) >> 5;
    int lane = threadIdx.x & 31;
    if (warp >= NN) return;
    int s = g_rowptr[warp];
    int e = g_rowptr[warp + 1];
    float4 acc = make_float4(0.f, 0.f, 0.f, 0.f);
    int i = s;
    for (; i + 2 <= e; i += 2) {
        int s0 = g_srclist[i];
        int s1 = g_srclist[i + 1];
        float4 v0 = *(const float4*)(g_h + (size_t)s0 * C + lane * 4);
        float4 v1 = *(const float4*)(g_h + (size_t)s1 * C + lane * 4);
        acc.x += v0.x + v1.x;  acc.y += v0.y + v1.y;
        acc.z += v0.z + v1.z;  acc.w += v0.w + v1.w;
    }
    if (i < e) {
        int s0 = g_srclist[i];
        float4 v0 = *(const float4*)(g_h + (size_t)s0 * C + lane * 4);
        acc.x += v0.x;  acc.y += v0.y;  acc.z += v0.z;  acc.w += v0.w;
    }
    float sc = 1.0f / fmaxf((float)(e - s), 1.0f);
    acc.x *= sc;  acc.y *= sc;  acc.z *= sc;  acc.w *= sc;
    *(float4*)(g_hbar + (size_t)warp * C + lane * 4) = acc;
}

// ================= mma.sync m16n8k16 bf16 =================
__device__ __forceinline__ void mma16816(float* c, const uint32_t* a, const uint32_t* b) {
    asm volatile(
        "mma.sync.aligned.m16n8k16.row.col.f32.bf16.bf16.f32 "
        "{%0,%1,%2,%3}, {%4,%5,%6,%7}, {%8,%9}, {%0,%1,%2,%3};"
        : "+f"(c[0]), "+f"(c[1]), "+f"(c[2]), "+f"(c[3])
        : "r"(a[0]), "r"(a[1]), "r"(a[2]), "r"(a[3]), "r"(b[0]), "r"(b[1]));
}

// 3-pass split-bf16 fragment GEMM, accumulates into acc[8][4]
// A: 64 rows x 128 K (hi/lo), B: 128 n x 128 K (hi/lo). Warp = (wm, wn), warp tile 16x64.
__device__ __forceinline__ void gemm_frag(const uint32_t* __restrict__ AH,
                                          const uint32_t* __restrict__ AL,
                                          const uint32_t* __restrict__ BH,
                                          const uint32_t* __restrict__ BL,
                                          int wm, int wn, int gr, int tig,
                                          float acc[8][4]) {
    const uint32_t* Aps[3] = {AH, AH, AL};
    const uint32_t* Bps[3] = {BH, BL, BH};
#pragma unroll
    for (int p = 0; p < 3; p++) {
        const uint32_t* __restrict__ Ab = Aps[p];
        const uint32_t* __restrict__ Bb = Bps[p];
#pragma unroll
        for (int ks = 0; ks < 8; ks++) {
            uint32_t a[4];
            int r0 = wm * 16 + gr;
            int abase = r0 * TSTR + ks * 8 + tig;
            a[0] = Ab[abase];
            a[1] = Ab[abase + 8 * TSTR];
            a[2] = Ab[abase + 4];
            a[3] = Ab[abase + 8 * TSTR + 4];
#pragma unroll
            for (int ni = 0; ni < 8; ni++) {
                int n0 = wn * 64 + ni * 8 + gr;
                int bbase = n0 * TSTR + ks * 8 + tig;
                uint32_t b[2];
                b[0] = Bb[bbase];
                b[1] = Bb[bbase + 4];
                mma16816(acc[ni], a, b);
            }
        }
    }
}

// ================= fused gi-GEMM + gh-GEMM + GRU gate =================
// h[rows] = GRU(hbar@Wfused_l + b_ih, h@w_hh^T + b_hh) computed in 3 column chunks.
// smem: Ab(hi/lo) + Ah(hi/lo) [64x68 each] + Bgi(hi/lo) + Bgh(hi/lo) [128x68 each]
#define FUSED_SMEM ((4 * A_WORDS + 4 * TILE_WORDS) * 4)   // 208896 B

__global__ void __launch_bounds__(256, 1)
fused_kernel(int layer, const float* __restrict__ bias_i, const float* __restrict__ bias_h)
{
    extern __shared__ uint32_t sm[];
    uint32_t* AbH = sm;
    uint32_t* AbL = sm + A_WORDS;
    uint32_t* AhH = sm + 2 * A_WORDS;
    uint32_t* AhL = sm + 3 * A_WORDS;
    uint32_t* BiH = sm + 4 * A_WORDS;
    uint32_t* BiL = BiH + TILE_WORDS;
    uint32_t* BhH = BiL + TILE_WORDS;
    uint32_t* BhL = BhH + TILE_WORDS;

    int tid = threadIdx.x;
    int rowBase = blockIdx.x * NROW;

    // ---- A tiles: convert hbar and h to split-bf16 padded layout ----
    for (int i = tid; i < NROW * 32; i += 256) {
        int row = i >> 5;
        int k2  = (i & 31) * 2;
        int grr = rowBase + row;
        float4 vb = make_float4(0.f, 0.f, 0.f, 0.f);
        float4 vh = make_float4(0.f, 0.f, 0.f, 0.f);
        if (grr < NN) {
            vb = *(const float4*)(g_hbar + (size_t)grr * C + k2 * 2);
            vh = *(const float4*)(g_h   + (size_t)grr * C + k2 * 2);
        }
        int o = row * TSTR + k2;
        {
            __nv_bfloat162 h0, h1, l0, l1;
            h0.x = __float2bfloat16_rn(vb.x);  h0.y = __float2bfloat16_rn(vb.y);
            h1.x = __float2bfloat16_rn(vb.z);  h1.y = __float2bfloat16_rn(vb.w);
            l0.x = __float2bfloat16_rn(vb.x - __bfloat162float(h0.x));
            l0.y = __float2bfloat16_rn(vb.y - __bfloat162float(h0.y));
            l1.x = __float2bfloat16_rn(vb.z - __bfloat162float(h1.x));
            l1.y = __float2bfloat16_rn(vb.w - __bfloat162float(h1.y));
            *(uint2*)(AbH + o) = make_uint2(*(uint32_t*)&h0, *(uint32_t*)&h1);
            *(uint2*)(AbL + o) = make_uint2(*(uint32_t*)&l0, *(uint32_t*)&l1);
        }
        {
            __nv_bfloat162 h0, h1, l0, l1;
            h0.x = __float2bfloat16_rn(vh.x);  h0.y = __float2bfloat16_rn(vh.y);
            h1.x = __float2bfloat16_rn(vh.z);  h1.y = __float2bfloat16_rn(vh.w);
            l0.x = __float2bfloat16_rn(vh.x - __bfloat162float(h0.x));
            l0.y = __float2bfloat16_rn(vh.y - __bfloat162float(h0.y));
            l1.x = __float2bfloat16_rn(vh.z - __bfloat162float(h1.x));
            l1.y = __float2bfloat16_rn(vh.w - __bfloat162float(h1.y));
            *(uint2*)(AhH + o) = make_uint2(*(uint32_t*)&h0, *(uint32_t*)&h1);
            *(uint2*)(AhL + o) = make_uint2(*(uint32_t*)&l0, *(uint32_t*)&l1);
        }
    }

    int wid = tid >> 5, lane = tid & 31;
    int gr = lane >> 2, tig = lane & 3;
    int wm = wid >> 1, wn = wid & 1;

    float rf[8][4], zf[8][4];

#pragma unroll
    for (int chunk = 0; chunk < 3; chunk++) {
        __syncthreads();   // A ready (chunk 0) / previous chunk's B readers done
        // ---- copy B tiles for this chunk (gi and gh, hi+lo) ----
        {
            int tgi = layer * 3 + chunk;
            int tgh = 9 + chunk;
            const float4* si_h = (const float4*)(g_btile_hi + (size_t)tgi * TILE_WORDS);
            const float4* si_l = (const float4*)(g_btile_lo + (size_t)tgi * TILE_WORDS);
            const float4* sh_h = (const float4*)(g_btile_hi + (size_t)tgh * TILE_WORDS);
            const float4* sh_l = (const float4*)(g_btile_lo + (size_t)tgh * TILE_WORDS);
            float4* dih = (float4*)BiH;  float4* dil = (float4*)BiL;
            float4* dhh = (float4*)BhH;  float4* dhl = (float4*)BhL;
            for (int i = tid; i < TILE_WORDS / 4; i += 256) {
                dih[i] = si_h[i];  dil[i] = si_l[i];
                dhh[i] = sh_h[i];  dhl[i] = sh_l[i];
            }
        }
        __syncthreads();

        if (chunk < 2) {
            // gi + gh accumulated together -> gate value directly
            float acc[8][4];
#pragma unroll
            for (int ni = 0; ni < 8; ni++)
#pragma unroll
                for (int q = 0; q < 4; q++) acc[ni][q] = 0.f;
            gemm_frag(AbH, AbL, BiH, BiL, wm, wn, gr, tig, acc);
            gemm_frag(AhH, AhL, BhH, BhL, wm, wn, gr, tig, acc);
#pragma unroll
            for (int ni = 0; ni < 8; ni++) {
                int cc = wn * 64 + ni * 8 + tig * 2;
#pragma unroll
                for (int q = 0; q < 4; q++) {
                    int col = chunk * 128 + cc + (q & 1);
                    float v = acc[ni][q] + bias_i[col] + bias_h[col];
                    float s = 1.0f / (1.0f + __expf(-v));
                    if (chunk == 0) rf[ni][q] = s; else zf[ni][q] = s;
                }
            }
        } else {
            // n-chunk: need gi and gh separately (n = tanh(i_n + r * h_n))
            float agi[8][4], agh[8][4];
#pragma unroll
            for (int ni = 0; ni < 8; ni++)
#pragma unroll
                for (int q = 0; q < 4; q++) { agi[ni][q] = 0.f; agh[ni][q] = 0.f; }
            gemm_frag(AbH, AbL, BiH, BiL, wm, wn, gr, tig, agi);
            gemm_frag(AhH, AhL, BhH, BhL, wm, wn, gr, tig, agh);

            int r0 = rowBase + wm * 16 + gr;
            int r1 = r0 + 8;
#pragma unroll
            for (int ni = 0; ni < 8; ni++) {
                int cc = wn * 64 + ni * 8 + tig * 2;     // output h column (0..127)
                float bi0 = bias_i[256 + cc],     bh0 = bias_h[256 + cc];
                float bi1 = bias_i[256 + cc + 1], bh1 = bias_h[256 + cc + 1];
                if (r0 < NN) {
                    float2 ho = *(const float2*)(g_h + (size_t)r0 * C + cc);
                    float n0 = tanhf(agi[ni][0] + bi0 + rf[ni][0] * (agh[ni][0] + bh0));
                    float n1 = tanhf(agi[ni][1] + bi1 + rf[ni][1] * (agh[ni][1] + bh1));
                    float2 hn;
                    hn.x = (1.0f - zf[ni][0]) * n0 + zf[ni][0] * ho.x;
                    hn.y = (1.0f - zf[ni][1]) * n1 + zf[ni][1] * ho.y;
                    *(float2*)(g_h + (size_t)r0 * C + cc) = hn;
                }
                if (r1 < NN) {
                    float2 ho = *(const float2*)(g_h + (size_t)r1 * C + cc);
                    float n2 = tanhf(agi[ni][2] + bi0 + rf[ni][2] * (agh[ni][2] + bh0));
                    float n3 = tanhf(agi[ni][3] + bi1 + rf[ni][3] * (agh[ni][3] + bh1));
                    float2 hn;
                    hn.x = (1.0f - zf[ni][2]) * n2 + zf[ni][2] * ho.x;
                    hn.y = (1.0f - zf[ni][3]) * n3 + zf[ni][3] * ho.y;
                    *(float2*)(g_h + (size_t)r1 * C + cc) = hn;
                }
            }
        }
    }
}

// ================= final mean + tanh =================
__global__ void mean_tanh_kernel(float* __restrict__ out) {
    int gtid = blockIdx.x * blockDim.x + threadIdx.x;
    int node = gtid >> 5;
    int lane = threadIdx.x & 31;
    if (node < NN) {
        float4 v = *(const float4*)(g_h + (size_t)node * C + lane * 4);
        float s = v.x + v.y + v.z + v.w;
#pragma unroll
        for (int o = 16; o > 0; o >>= 1) s += __shfl_down_sync(0xffffffffu, s, o);
        if (lane == 0) out[node] = tanhf(s * (1.0f / 128.0f));
    }
}

// ================= launch =================
extern "C" void kernel_launch(void* const* d_in, const int* in_sizes, int n_in,
                              void* d_out, int out_size) {
    int ix = 0, ie = 1, iw = 2, iwih = 3, iwhh = 4, ibih = 5, ibhh = 6;
    {
        int w_seen = 0, b_seen = 0;
        for (int i = 0; i < n_in; i++) {
            long long s = in_sizes[i];
            if (s == (long long)NN * C) ix = i;
            else if (s == 2LL * NE) ie = i;
            else if (s == (long long)C3 * C) {
                if (w_seen == 0) iw = i;
                else if (w_seen == 1) iwih = i;
                else if (w_seen == 2) iwhh = i;
                w_seen++;
            } else if (s == C3) {
                if (b_seen == 0) ibih = i;
                else if (b_seen == 1) ibhh = i;
                b_seen++;
            }
        }
    }
    const float* x      = (const float*)d_in[ix];
    const void*  ei     = d_in[ie];
    const float* weight = (const float*)d_in[iw];
    const float* w_ih   = (const float*)d_in[iwih];
    const float* w_hh   = (const float*)d_in[iwhh];
    const float* b_ih   = (const float*)d_in[ibih];
    const float* b_hh   = (const float*)d_in[ibhh];
    float*       out    = (float*)d_out;

    static bool attr_set = false;
    if (!attr_set) {
        cudaFuncSetAttribute(fused_kernel, cudaFuncAttributeMaxDynamicSharedMemorySize, FUSED_SMEM);
        attr_set = true;
    }

    const int NC = NN * C;
    detect_kernel<<<1, 32>>>((const unsigned int*)ei);
    init_h_kernel<<<(NC + 255) / 256, 256>>>(x);
    zero_deg_kernel<<<(NN + 255) / 256, 256>>>();
    count_kernel<<<(NE + 255) / 256, 256>>>(ei);
    scanA_kernel<<<SCAN_NB, SCAN_B>>>();
    scanB_kernel<<<1, 32>>>();
    scanC_kernel<<<SCAN_NB, SCAN_B>>>();
    fill_kernel<<<(NE + 255) / 256, 256>>>(ei);
    wfused_kernel<<<(3 * 128 * 384 + 255) / 256, 256>>>(weight, w_ih);
    prep_btiles_kernel<<<(12 * 128 * 64 + 255) / 256, 256>>>(w_hh);

    int gather_blocks = (NN * 32 + 255) / 256;
    int fused_blocks = (NN + NROW - 1) / NROW;   // 1563

    for (int l = 0; l < NLAYERS; l++) {
        gather_kernel<<<gather_blocks, 256>>>();
        fused_kernel<<<fused_blocks, 256, FUSED_SMEM>>>(l, b_ih, b_hh);
    }

    mean_tanh_kernel<<<(NN * 32 + 255) / 256, 256>>>(out);
}

// round 10
// speedup vs baseline: 2.5387x; 1.5769x over previous
#include <cuda_runtime.h>
#include <cuda_fp16.h>
#include <cstdint>

#define NN 100000
#define NE 1600000
#define C 128
#define C3 384
#define NLAYERS 3
#define SCAN_B 512
#define SCAN_NB ((NN + SCAN_B - 1) / SCAN_B)   // 196

// padded tile layout: [rows][68 uint32 words] (64 used = 128 fp16, +4 pad)
#define TSTR 68
#define TILE_WORDS (128 * TSTR)       // B tiles: 128 n-rows  (34816 B)
#define NROW 64                       // fused-kernel CTA rows
#define A_WORDS (NROW * TSTR)         // A tiles: 64 rows     (17408 B)

// ================= scratch (device globals; no allocation allowed) =================
__device__ __align__(256) float    g_h[NN * C];          // hidden state fp32
__device__ __align__(256) uint32_t g_h16[NN * 64];       // fp16 mirror of h (half2 words)
__device__ __align__(256) uint32_t g_hbar16[NN * 64];    // fp16 mean-pooled neighbor h
__device__ __align__(256) float    g_wfused[3 * 128 * 384];  // W_l @ w_ih^T (fp32)
// fp16 padded B tiles: 0-8 = Wfused (layer*3+chunk), 9-11 = w_hh chunks
__device__ __align__(256) uint32_t g_btile[12 * TILE_WORDS];
// CSR build
__device__ __align__(256) int g_deg[NN];
__device__ __align__(256) int g_bsum[SCAN_NB];
__device__ __align__(256) int g_rowptr[NN + 1];
__device__ __align__(256) int g_cur[NN];
__device__ __align__(256) int g_srclist[NE];
__device__ int g_is64;

// ================= helpers =================
__device__ __forceinline__ uint32_t smem_to_u32(const void* p) {
    uint32_t a;
    asm("{ .reg .u64 t; cvta.to.shared.u64 t, %1; cvt.u32.u64 %0, t; }" : "=r"(a) : "l"(p));
    return a;
}
__device__ __forceinline__ void cp_async16(uint32_t saddr, const void* gaddr) {
    asm volatile("cp.async.cg.shared.global [%0], [%1], 16;" :: "r"(saddr), "l"(gaddr));
}
#define CP_COMMIT() asm volatile("cp.async.commit_group;" ::: "memory")
#define CP_WAIT(n)  asm volatile("cp.async.wait_group %0;" :: "n"(n) : "memory")

__device__ __forceinline__ uint32_t pack_h2(float a, float b) {
    __half2 h = __floats2half2_rn(a, b);
    return *(uint32_t*)&h;
}

// ================= dtype detection (edge_index int64 vs int32) =================
__global__ void detect_kernel(const unsigned int* __restrict__ ei32) {
    if (blockIdx.x == 0 && threadIdx.x == 0) {
        int is64 = 1;
        for (int i = 1; i < 64; i += 2)
            if (ei32[i] != 0u) { is64 = 0; break; }
        g_is64 = is64;
    }
}
__device__ __forceinline__ int load_edge(const void* ei, long long idx) {
    int v;
    if (g_is64) v = (int)((const long long*)ei)[idx];
    else        v = ((const int*)ei)[idx];
    return min(max(v, 0), NN - 1);
}

// ================= init / CSR build =================
__global__ void init_h_kernel(const float* __restrict__ x) {
    int i = blockIdx.x * blockDim.x + threadIdx.x;   // over NN*64 word pairs
    if (i < NN * 64) {
        float2 v = ((const float2*)x)[i];
        ((float2*)g_h)[i] = v;
        g_h16[i] = pack_h2(v.x, v.y);
    }
}
__global__ void zero_deg_kernel() {
    int i = blockIdx.x * blockDim.x + threadIdx.x;
    if (i < NN) g_deg[i] = 0;
}
__global__ void count_kernel(const void* __restrict__ ei) {
    int e = blockIdx.x * blockDim.x + threadIdx.x;
    if (e < NE) atomicAdd(&g_deg[load_edge(ei, (long long)NE + e)], 1);
}
__global__ void scanA_kernel() {
    __shared__ int sh[SCAN_B];
    int i = blockIdx.x * SCAN_B + threadIdx.x;
    sh[threadIdx.x] = (i < NN) ? g_deg[i] : 0;
    __syncthreads();
    for (int off = SCAN_B / 2; off > 0; off >>= 1) {
        if (threadIdx.x < off) sh[threadIdx.x] += sh[threadIdx.x + off];
        __syncthreads();
    }
    if (threadIdx.x == 0) g_bsum[blockIdx.x] = sh[0];
}
__global__ void scanB_kernel() {
    if (threadIdx.x == 0 && blockIdx.x == 0) {
        int run = 0;
        for (int b = 0; b < SCAN_NB; b++) { int v = g_bsum[b]; g_bsum[b] = run; run += v; }
    }
}
__global__ void scanC_kernel() {
    __shared__ int sh[SCAN_B];
    int i = blockIdx.x * SCAN_B + threadIdx.x;
    int v = (i < NN) ? g_deg[i] : 0;
    sh[threadIdx.x] = v;
    __syncthreads();
    for (int off = 1; off < SCAN_B; off <<= 1) {
        int t = (threadIdx.x >= off) ? sh[threadIdx.x - off] : 0;
        __syncthreads();
        sh[threadIdx.x] += t;
        __syncthreads();
    }
    if (i < NN) {
        int excl = sh[threadIdx.x] - v + g_bsum[blockIdx.x];
        g_rowptr[i] = excl;
        g_cur[i] = excl;
    }
    if (i == NN - 1) g_rowptr[NN] = NE;
}
__global__ void fill_kernel(const void* __restrict__ ei) {
    int e = blockIdx.x * blockDim.x + threadIdx.x;
    if (e < NE) {
        int src = load_edge(ei, e);
        int dst = load_edge(ei, (long long)NE + e);
        int pos = atomicAdd(&g_cur[dst], 1);
        if (pos >= 0 && pos < NE) g_srclist[pos] = src;
    }
}

// ================= Wfused = W_l @ w_ih^T (fp32, once) =================
__global__ void wfused_kernel(const float* __restrict__ weight,
                              const float* __restrict__ w_ih) {
    int idx = blockIdx.x * blockDim.x + threadIdx.x;   // l*49152 + k*384 + n
    if (idx >= 3 * 128 * 384) return;
    int l = idx / 49152;
    int rem = idx % 49152;
    int k = rem / 384;
    int n = rem % 384;
    const float* wl = weight + l * 16384 + k * 128;
    const float* wr = w_ih + (size_t)n * 128;
    float s = 0.f;
#pragma unroll 8
    for (int j = 0; j < 128; j++) s += wl[j] * wr[j];
    g_wfused[idx] = s;
}

// ================= B-tile prep: fp16 padded images =================
__global__ void prep_btiles_kernel(const float* __restrict__ w_hh) {
    int idx = blockIdx.x * blockDim.x + threadIdx.x;   // over 12 * 128 * 64
    if (idx >= 12 * 128 * 64) return;
    int tile = idx >> 13;
    int rem  = idx & 8191;
    int n  = rem >> 6;
    int k2 = rem & 63;
    float v0, v1;
    if (tile < 9) {
        int l = tile / 3, chunk = tile % 3;
        const float* base = g_wfused + l * 49152 + chunk * 128 + n;
        v0 = base[(k2 * 2) * 384];
        v1 = base[(k2 * 2 + 1) * 384];
    } else {
        const float* r = w_hh + ((size_t)((tile - 9) * 128 + n)) * 128;
        v0 = r[k2 * 2];  v1 = r[k2 * 2 + 1];
    }
    g_btile[(size_t)tile * TILE_WORDS + n * TSTR + k2] = pack_h2(v0, v1);
}

// ================= gather: hbar16 = mean of h16 over in-neighbors =================
__global__ void gather_kernel() {
    int warp = (blockIdx.x * blockDim.x + threadIdx.x) >> 5;
    int lane = threadIdx.x & 31;
    if (warp >= NN) return;
    int s = g_rowptr[warp];
    int e = g_rowptr[warp + 1];
    float4 acc = make_float4(0.f, 0.f, 0.f, 0.f);
    int i = s;
    for (; i + 2 <= e; i += 2) {
        int s0 = g_srclist[i];
        int s1 = g_srclist[i + 1];
        uint2 w0 = *(const uint2*)(g_h16 + (size_t)s0 * 64 + lane * 2);
        uint2 w1 = *(const uint2*)(g_h16 + (size_t)s1 * 64 + lane * 2);
        float2 a0 = __half22float2(*(__half2*)&w0.x);
        float2 a1 = __half22float2(*(__half2*)&w0.y);
        float2 b0 = __half22float2(*(__half2*)&w1.x);
        float2 b1 = __half22float2(*(__half2*)&w1.y);
        acc.x += a0.x + b0.x;  acc.y += a0.y + b0.y;
        acc.z += a1.x + b1.x;  acc.w += a1.y + b1.y;
    }
    if (i < e) {
        int s0 = g_srclist[i];
        uint2 w0 = *(const uint2*)(g_h16 + (size_t)s0 * 64 + lane * 2);
        float2 a0 = __half22float2(*(__half2*)&w0.x);
        float2 a1 = __half22float2(*(__half2*)&w0.y);
        acc.x += a0.x;  acc.y += a0.y;  acc.z += a1.x;  acc.w += a1.y;
    }
    float sc = 1.0f / fmaxf((float)(e - s), 1.0f);
    uint2 outw;
    outw.x = pack_h2(acc.x * sc, acc.y * sc);
    outw.y = pack_h2(acc.z * sc, acc.w * sc);
    *(uint2*)(g_hbar16 + (size_t)warp * 64 + lane * 2) = outw;
}

// ================= mma.sync m16n8k16 fp16 =================
__device__ __forceinline__ void mma16816(float* c, const uint32_t* a, const uint32_t* b) {
    asm volatile(
        "mma.sync.aligned.m16n8k16.row.col.f32.f16.f16.f32 "
        "{%0,%1,%2,%3}, {%4,%5,%6,%7}, {%8,%9}, {%0,%1,%2,%3};"
        : "+f"(c[0]), "+f"(c[1]), "+f"(c[2]), "+f"(c[3])
        : "r"(a[0]), "r"(a[1]), "r"(a[2]), "r"(a[3]), "r"(b[0]), "r"(b[1]));
}

// single-pass fragment GEMM, accumulates into acc[8][4]
// A: 64 rows x 128 K fp16; B: 128 n x 128 K fp16. Warp (wm, wn), warp tile 16x64.
__device__ __forceinline__ void gemm_frag(const uint32_t* __restrict__ Ab,
                                          const uint32_t* __restrict__ Bb,
                                          int wm, int wn, int gr, int tig,
                                          float acc[8][4]) {
#pragma unroll
    for (int ks = 0; ks < 8; ks++) {
        uint32_t a[4];
        int abase = (wm * 16 + gr) * TSTR + ks * 8 + tig;
        a[0] = Ab[abase];
        a[1] = Ab[abase + 8 * TSTR];
        a[2] = Ab[abase + 4];
        a[3] = Ab[abase + 8 * TSTR + 4];
#pragma unroll
        for (int ni = 0; ni < 8; ni++) {
            int bbase = (wn * 64 + ni * 8 + gr) * TSTR + ks * 8 + tig;
            uint32_t b[2];
            b[0] = Bb[bbase];
            b[1] = Bb[bbase + 4];
            mma16816(acc[ni], a, b);
        }
    }
}

// ================= fused gi-GEMM + gh-GEMM + GRU gate =================
// smem: Ab, Ah (64x68 words) + Bbuf0, Bbuf1 (each Bi+Bh = 2*128x68 words)
#define FUSED_SMEM ((2 * A_WORDS + 4 * TILE_WORDS) * 4)   // 174080 B

__device__ __forceinline__ void prefetch_chunk(uint32_t sB, int layer, int chunk, int tid) {
    const uint32_t* srcI = g_btile + (size_t)(layer * 3 + chunk) * TILE_WORDS;
    const uint32_t* srcH = g_btile + (size_t)(9 + chunk) * TILE_WORDS;
    for (int i = tid * 4; i < TILE_WORDS; i += 256 * 4) {
        cp_async16(sB + i * 4, srcI + i);
        cp_async16(sB + (TILE_WORDS + i) * 4, srcH + i);
    }
    CP_COMMIT();
}

__global__ void __launch_bounds__(256, 1)
fused_kernel(int layer, const float* __restrict__ bias_i, const float* __restrict__ bias_h)
{
    extern __shared__ uint32_t sm[];
    uint32_t* Ab = sm;
    uint32_t* Ah = sm + A_WORDS;
    uint32_t* B0 = sm + 2 * A_WORDS;
    uint32_t* B1 = B0 + 2 * TILE_WORDS;
    uint32_t sB0 = smem_to_u32(B0);
    uint32_t sB1 = smem_to_u32(B1);

    int tid = threadIdx.x;
    int rowBase = blockIdx.x * NROW;

    // prefetch chunk 0 and 1 B tiles (overlaps with A relayout below)
    prefetch_chunk(sB0, layer, 0, tid);
    prefetch_chunk(sB1, layer, 1, tid);

    // ---- A tiles: relayout fp16 hbar/h into padded smem ----
    for (int i = tid; i < NROW * 16; i += 256) {
        int row = i >> 4;
        int q4  = (i & 15) * 4;          // word offset (16B chunks)
        int grr = rowBase + row;
        uint4 vb = make_uint4(0u, 0u, 0u, 0u);
        uint4 vh = make_uint4(0u, 0u, 0u, 0u);
        if (grr < NN) {
            vb = *(const uint4*)(g_hbar16 + (size_t)grr * 64 + q4);
            vh = *(const uint4*)(g_h16   + (size_t)grr * 64 + q4);
        }
        int o = row * TSTR + q4;
        *(uint4*)(Ab + o) = vb;
        *(uint4*)(Ah + o) = vh;
    }

    int wid = tid >> 5, lane = tid & 31;
    int gr = lane >> 2, tig = lane & 3;
    int wm = wid >> 1, wn = wid & 1;

    float rf[8][4], zf[8][4];

#pragma unroll
    for (int chunk = 0; chunk < 3; chunk++) {
        if (chunk < 2) { CP_WAIT(1); } else { CP_WAIT(0); }
        __syncthreads();   // B chunk ready + (chunk0) A ready / prior readers done
        uint32_t* Bi = (chunk == 1) ? B1 : B0;
        uint32_t* Bh = Bi + TILE_WORDS;

        if (chunk < 2) {
            float acc[8][4];
#pragma unroll
            for (int ni = 0; ni < 8; ni++)
#pragma unroll
                for (int q = 0; q < 4; q++) acc[ni][q] = 0.f;
            gemm_frag(Ab, Bi, wm, wn, gr, tig, acc);
            gemm_frag(Ah, Bh, wm, wn, gr, tig, acc);
#pragma unroll
            for (int ni = 0; ni < 8; ni++) {
                int cc = wn * 64 + ni * 8 + tig * 2;
#pragma unroll
                for (int q = 0; q < 4; q++) {
                    int col = chunk * 128 + cc + (q & 1);
                    float v = acc[ni][q] + bias_i[col] + bias_h[col];
                    float s = 1.0f / (1.0f + __expf(-v));
                    if (chunk == 0) rf[ni][q] = s; else zf[ni][q] = s;
                }
            }
            if (chunk == 0) {
                __syncthreads();                    // all warps done reading B0
                prefetch_chunk(sB0, layer, 2, tid); // chunk 2 -> buffer 0
            }
        } else {
            float agi[8][4], agh[8][4];
#pragma unroll
            for (int ni = 0; ni < 8; ni++)
#pragma unroll
                for (int q = 0; q < 4; q++) { agi[ni][q] = 0.f; agh[ni][q] = 0.f; }
            gemm_frag(Ab, Bi, wm, wn, gr, tig, agi);
            gemm_frag(Ah, Bh, wm, wn, gr, tig, agh);

            int r0 = rowBase + wm * 16 + gr;
            int r1 = r0 + 8;
#pragma unroll
            for (int ni = 0; ni < 8; ni++) {
                int cc = wn * 64 + ni * 8 + tig * 2;
                float bi0 = bias_i[256 + cc],     bh0 = bias_h[256 + cc];
                float bi1 = bias_i[256 + cc + 1], bh1 = bias_h[256 + cc + 1];
                if (r0 < NN) {
                    float2 ho = *(const float2*)(g_h + (size_t)r0 * C + cc);
                    float n0 = tanhf(agi[ni][0] + bi0 + rf[ni][0] * (agh[ni][0] + bh0));
                    float n1 = tanhf(agi[ni][1] + bi1 + rf[ni][1] * (agh[ni][1] + bh1));
                    float2 hn;
                    hn.x = (1.0f - zf[ni][0]) * n0 + zf[ni][0] * ho.x;
                    hn.y = (1.0f - zf[ni][1]) * n1 + zf[ni][1] * ho.y;
                    *(float2*)(g_h + (size_t)r0 * C + cc) = hn;
                    g_h16[(size_t)r0 * 64 + (cc >> 1)] = pack_h2(hn.x, hn.y);
                }
                if (r1 < NN) {
                    float2 ho = *(const float2*)(g_h + (size_t)r1 * C + cc);
                    float n2 = tanhf(agi[ni][2] + bi0 + rf[ni][2] * (agh[ni][2] + bh0));
                    float n3 = tanhf(agi[ni][3] + bi1 + rf[ni][3] * (agh[ni][3] + bh1));
                    float2 hn;
                    hn.x = (1.0f - zf[ni][2]) * n2 + zf[ni][2] * ho.x;
                    hn.y = (1.0f - zf[ni][3]) * n3 + zf[ni][3] * ho.y;
                    *(float2*)(g_h + (size_t)r1 * C + cc) = hn;
                    g_h16[(size_t)r1 * 64 + (cc >> 1)] = pack_h2(hn.x, hn.y);
                }
            }
        }
    }
}

// ================= final mean + tanh =================
__global__ void mean_tanh_kernel(float* __restrict__ out) {
    int gtid = blockIdx.x * blockDim.x + threadIdx.x;
    int node = gtid >> 5;
    int lane = threadIdx.x & 31;
    if (node < NN) {
        float4 v = *(const float4*)(g_h + (size_t)node * C + lane * 4);
        float s = v.x + v.y + v.z + v.w;
#pragma unroll
        for (int o = 16; o > 0; o >>= 1) s += __shfl_down_sync(0xffffffffu, s, o);
        if (lane == 0) out[node] = tanhf(s * (1.0f / 128.0f));
    }
}

// ================= launch =================
extern "C" void kernel_launch(void* const* d_in, const int* in_sizes, int n_in,
                              void* d_out, int out_size) {
    int ix = 0, ie = 1, iw = 2, iwih = 3, iwhh = 4, ibih = 5, ibhh = 6;
    {
        int w_seen = 0, b_seen = 0;
        for (int i = 0; i < n_in; i++) {
            long long s = in_sizes[i];
            if (s == (long long)NN * C) ix = i;
            else if (s == 2LL * NE) ie = i;
            else if (s == (long long)C3 * C) {
                if (w_seen == 0) iw = i;
                else if (w_seen == 1) iwih = i;
                else if (w_seen == 2) iwhh = i;
                w_seen++;
            } else if (s == C3) {
                if (b_seen == 0) ibih = i;
                else if (b_seen == 1) ibhh = i;
                b_seen++;
            }
        }
    }
    const float* x      = (const float*)d_in[ix];
    const void*  ei     = d_in[ie];
    const float* weight = (const float*)d_in[iw];
    const float* w_ih   = (const float*)d_in[iwih];
    const float* w_hh   = (const float*)d_in[iwhh];
    const float* b_ih   = (const float*)d_in[ibih];
    const float* b_hh   = (const float*)d_in[ibhh];
    float*       out    = (float*)d_out;

    static bool attr_set = false;
    if (!attr_set) {
        cudaFuncSetAttribute(fused_kernel, cudaFuncAttributeMaxDynamicSharedMemorySize, FUSED_SMEM);
        attr_set = true;
    }

    detect_kernel<<<1, 32>>>((const unsigned int*)ei);
    init_h_kernel<<<(NN * 64 + 255) / 256, 256>>>(x);
    zero_deg_kernel<<<(NN + 255) / 256, 256>>>();
    count_kernel<<<(NE + 255) / 256, 256>>>(ei);
    scanA_kernel<<<SCAN_NB, SCAN_B>>>();
    scanB_kernel<<<1, 32>>>();
    scanC_kernel<<<SCAN_NB, SCAN_B>>>();
    fill_kernel<<<(NE + 255) / 256, 256>>>(ei);
    wfused_kernel<<<(3 * 128 * 384 + 255) / 256, 256>>>(weight, w_ih);
    prep_btiles_kernel<<<(12 * 128 * 64 + 255) / 256, 256>>>(w_hh);

    int gather_blocks = (NN * 32 + 255) / 256;
    int fused_blocks = (NN + NROW - 1) / NROW;   // 1563

    for (int l = 0; l < NLAYERS; l++) {
        gather_kernel<<<gather_blocks, 256>>>();
        fused_kernel<<<fused_blocks, 256, FUSED_SMEM>>>(l, b_ih, b_hh);
    }

    mean_tanh_kernel<<<(NN * 32 + 255) / 256, 256>>>(out);
}

// round 11
// speedup vs baseline: 3.2171x; 1.2672x over previous
#include <cuda_runtime.h>
#include <cuda_fp16.h>
#include <cstdint>

#define NN 100000
#define NE 1600000
#define C 128
#define C3 384
#define NLAYERS 3
#define SCAN_B 512
#define SCAN_NB ((NN + SCAN_B - 1) / SCAN_B)   // 196

// padded tile layout: [rows][68 uint32 words] (64 used = 128 fp16, +4 pad)
#define TSTR 68
#define TILE_WORDS (128 * TSTR)       // B tiles: 128 n-rows  (34816 B)
#define NROW 64                       // fused-kernel CTA rows
#define A_WORDS (NROW * TSTR)         // A tiles: 64 rows     (17408 B)

// ================= scratch (device globals; no allocation allowed) =================
__device__ __align__(256) float    g_h[NN * C];          // hidden state fp32
__device__ __align__(256) uint32_t g_h16[NN * 64];       // fp16 mirror of h (half2 words)
__device__ __align__(256) uint32_t g_hbar16[NN * 64];    // fp16 mean-pooled neighbor h
__device__ __align__(256) float    g_wfused[3 * 128 * 384];  // W_l @ w_ih^T (fp32)
// fp16 padded B tiles: 0-8 = Wfused (layer*3+chunk), 9-11 = w_hh chunks
__device__ __align__(256) uint32_t g_btile[12 * TILE_WORDS];
// CSR build
__device__ __align__(256) int g_deg[NN];
__device__ __align__(256) int g_bsum[SCAN_NB];
__device__ __align__(256) int g_rowptr[NN + 1];
__device__ __align__(256) int g_cur[NN];
__device__ __align__(256) int g_srclist[NE];
__device__ int g_is64;

// ================= helpers =================
__device__ __forceinline__ uint32_t smem_to_u32(const void* p) {
    uint32_t a;
    asm("{ .reg .u64 t; cvta.to.shared.u64 t, %1; cvt.u32.u64 %0, t; }" : "=r"(a) : "l"(p));
    return a;
}
__device__ __forceinline__ void cp_async16(uint32_t saddr, const void* gaddr) {
    asm volatile("cp.async.cg.shared.global [%0], [%1], 16;" :: "r"(saddr), "l"(gaddr));
}
#define CP_COMMIT() asm volatile("cp.async.commit_group;" ::: "memory")
#define CP_WAIT0()  asm volatile("cp.async.wait_group 0;" ::: "memory")

__device__ __forceinline__ uint32_t pack_h2(float a, float b) {
    __half2 h = __floats2half2_rn(a, b);
    return *(uint32_t*)&h;
}
__device__ __forceinline__ void ldmx4(uint32_t* r, uint32_t saddr) {
    asm volatile("ldmatrix.sync.aligned.m8n8.x4.shared.b16 {%0,%1,%2,%3}, [%4];"
                 : "=r"(r[0]), "=r"(r[1]), "=r"(r[2]), "=r"(r[3]) : "r"(saddr));
}

// ================= dtype detection (edge_index int64 vs int32) =================
__global__ void detect_kernel(const unsigned int* __restrict__ ei32) {
    if (blockIdx.x == 0 && threadIdx.x == 0) {
        int is64 = 1;
        for (int i = 1; i < 64; i += 2)
            if (ei32[i] != 0u) { is64 = 0; break; }
        g_is64 = is64;
    }
}
__device__ __forceinline__ int load_edge(const void* ei, long long idx) {
    int v;
    if (g_is64) v = (int)((const long long*)ei)[idx];
    else        v = ((const int*)ei)[idx];
    return min(max(v, 0), NN - 1);
}

// ================= init / CSR build =================
__global__ void init_h_kernel(const float* __restrict__ x) {
    int i = blockIdx.x * blockDim.x + threadIdx.x;
    if (i < NN * 64) {
        float2 v = ((const float2*)x)[i];
        ((float2*)g_h)[i] = v;
        g_h16[i] = pack_h2(v.x, v.y);
    }
}
__global__ void zero_deg_kernel() {
    int i = blockIdx.x * blockDim.x + threadIdx.x;
    if (i < NN) g_deg[i] = 0;
}
__global__ void count_kernel(const void* __restrict__ ei) {
    int e = blockIdx.x * blockDim.x + threadIdx.x;
    if (e < NE) atomicAdd(&g_deg[load_edge(ei, (long long)NE + e)], 1);
}
__global__ void scanA_kernel() {
    __shared__ int sh[SCAN_B];
    int i = blockIdx.x * SCAN_B + threadIdx.x;
    sh[threadIdx.x] = (i < NN) ? g_deg[i] : 0;
    __syncthreads();
    for (int off = SCAN_B / 2; off > 0; off >>= 1) {
        if (threadIdx.x < off) sh[threadIdx.x] += sh[threadIdx.x + off];
        __syncthreads();
    }
    if (threadIdx.x == 0) g_bsum[blockIdx.x] = sh[0];
}
__global__ void scanB_kernel() {
    if (threadIdx.x == 0 && blockIdx.x == 0) {
        int run = 0;
        for (int b = 0; b < SCAN_NB; b++) { int v = g_bsum[b]; g_bsum[b] = run; run += v; }
    }
}
__global__ void scanC_kernel() {
    __shared__ int sh[SCAN_B];
    int i = blockIdx.x * SCAN_B + threadIdx.x;
    int v = (i < NN) ? g_deg[i] : 0;
    sh[threadIdx.x] = v;
    __syncthreads();
    for (int off = 1; off < SCAN_B; off <<= 1) {
        int t = (threadIdx.x >= off) ? sh[threadIdx.x - off] : 0;
        __syncthreads();
        sh[threadIdx.x] += t;
        __syncthreads();
    }
    if (i < NN) {
        int excl = sh[threadIdx.x] - v + g_bsum[blockIdx.x];
        g_rowptr[i] = excl;
        g_cur[i] = excl;
    }
    if (i == NN - 1) g_rowptr[NN] = NE;
}
__global__ void fill_kernel(const void* __restrict__ ei) {
    int e = blockIdx.x * blockDim.x + threadIdx.x;
    if (e < NE) {
        int src = load_edge(ei, e);
        int dst = load_edge(ei, (long long)NE + e);
        int pos = atomicAdd(&g_cur[dst], 1);
        if (pos >= 0 && pos < NE) g_srclist[pos] = src;
    }
}

// ================= Wfused = W_l @ w_ih^T (fp32, once) =================
__global__ void wfused_kernel(const float* __restrict__ weight,
                              const float* __restrict__ w_ih) {
    int idx = blockIdx.x * blockDim.x + threadIdx.x;
    if (idx >= 3 * 128 * 384) return;
    int l = idx / 49152;
    int rem = idx % 49152;
    int k = rem / 384;
    int n = rem % 384;
    const float* wl = weight + l * 16384 + k * 128;
    const float* wr = w_ih + (size_t)n * 128;
    float s = 0.f;
#pragma unroll 8
    for (int j = 0; j < 128; j++) s += wl[j] * wr[j];
    g_wfused[idx] = s;
}

// ================= B-tile prep: fp16 padded images =================
__global__ void prep_btiles_kernel(const float* __restrict__ w_hh) {
    int idx = blockIdx.x * blockDim.x + threadIdx.x;
    if (idx >= 12 * 128 * 64) return;
    int tile = idx >> 13;
    int rem  = idx & 8191;
    int n  = rem >> 6;
    int k2 = rem & 63;
    float v0, v1;
    if (tile < 9) {
        int l = tile / 3, chunk = tile % 3;
        const float* base = g_wfused + l * 49152 + chunk * 128 + n;
        v0 = base[(k2 * 2) * 384];
        v1 = base[(k2 * 2 + 1) * 384];
    } else {
        const float* r = w_hh + ((size_t)((tile - 9) * 128 + n)) * 128;
        v0 = r[k2 * 2];  v1 = r[k2 * 2 + 1];
    }
    g_btile[(size_t)tile * TILE_WORDS + n * TSTR + k2] = pack_h2(v0, v1);
}

// ================= gather: hbar16 = mean of h16 over in-neighbors =================
__global__ void gather_kernel() {
    int warp = (blockIdx.x * blockDim.x + threadIdx.x) >> 5;
    int lane = threadIdx.x & 31;
    if (warp >= NN) return;
    int s = g_rowptr[warp];
    int e = g_rowptr[warp + 1];
    float4 acc = make_float4(0.f, 0.f, 0.f, 0.f);
    int i = s;
    for (; i + 4 <= e; i += 4) {
        int s0 = g_srclist[i],     s1 = g_srclist[i + 1];
        int s2 = g_srclist[i + 2], s3 = g_srclist[i + 3];
        uint2 w0 = *(const uint2*)(g_h16 + (size_t)s0 * 64 + lane * 2);
        uint2 w1 = *(const uint2*)(g_h16 + (size_t)s1 * 64 + lane * 2);
        uint2 w2 = *(const uint2*)(g_h16 + (size_t)s2 * 64 + lane * 2);
        uint2 w3 = *(const uint2*)(g_h16 + (size_t)s3 * 64 + lane * 2);
        float2 a0 = __half22float2(*(__half2*)&w0.x), a1 = __half22float2(*(__half2*)&w0.y);
        float2 b0 = __half22float2(*(__half2*)&w1.x), b1 = __half22float2(*(__half2*)&w1.y);
        float2 c0 = __half22float2(*(__half2*)&w2.x), c1 = __half22float2(*(__half2*)&w2.y);
        float2 d0 = __half22float2(*(__half2*)&w3.x), d1 = __half22float2(*(__half2*)&w3.y);
        acc.x += (a0.x + b0.x) + (c0.x + d0.x);
        acc.y += (a0.y + b0.y) + (c0.y + d0.y);
        acc.z += (a1.x + b1.x) + (c1.x + d1.x);
        acc.w += (a1.y + b1.y) + (c1.y + d1.y);
    }
    for (; i < e; i++) {
        int s0 = g_srclist[i];
        uint2 w0 = *(const uint2*)(g_h16 + (size_t)s0 * 64 + lane * 2);
        float2 a0 = __half22float2(*(__half2*)&w0.x), a1 = __half22float2(*(__half2*)&w0.y);
        acc.x += a0.x;  acc.y += a0.y;  acc.z += a1.x;  acc.w += a1.y;
    }
    float sc = 1.0f / fmaxf((float)(e - s), 1.0f);
    uint2 outw;
    outw.x = pack_h2(acc.x * sc, acc.y * sc);
    outw.y = pack_h2(acc.z * sc, acc.w * sc);
    *(uint2*)(g_hbar16 + (size_t)warp * 64 + lane * 2) = outw;
}

// ================= mma.sync m16n8k16 fp16 =================
__device__ __forceinline__ void mma16816(float* c, const uint32_t* a, const uint32_t* b) {
    asm volatile(
        "mma.sync.aligned.m16n8k16.row.col.f32.f16.f16.f32 "
        "{%0,%1,%2,%3}, {%4,%5,%6,%7}, {%8,%9}, {%0,%1,%2,%3};"
        : "+f"(c[0]), "+f"(c[1]), "+f"(c[2]), "+f"(c[3])
        : "r"(a[0]), "r"(a[1]), "r"(a[2]), "r"(a[3]), "r"(b[0]), "r"(b[1]));
}

// ldmatrix-based fragment GEMM. aAddr/bAddr: per-lane smem byte addresses (ks=0).
// B ni-pairs p: address bump p * 16 rows * TSTR words * 4 B.
__device__ __forceinline__ void gemm_frag(uint32_t aAddr, uint32_t bAddr, float acc[8][4]) {
#pragma unroll
    for (int ks = 0; ks < 8; ks++) {
        uint32_t a[4];
        ldmx4(a, aAddr + ks * 32);
#pragma unroll
        for (int p = 0; p < 4; p++) {
            uint32_t b[4];
            ldmx4(b, bAddr + p * (16 * TSTR * 4) + ks * 32);
            mma16816(acc[2 * p],     a, b);
            mma16816(acc[2 * p + 1], a, b + 2);
        }
    }
}

// ================= fused gi-GEMM + gh-GEMM + GRU gate =================
// smem: Ab, Ah (64x68 words) + B (Bi + Bh, 2*128x68 words) -> 104448 B, 2 CTAs/SM
#define FUSED_SMEM ((2 * A_WORDS + 2 * TILE_WORDS) * 4)

__device__ __forceinline__ void prefetch_chunk(uint32_t sB, int layer, int chunk, int tid) {
    const uint32_t* srcI = g_btile + (size_t)(layer * 3 + chunk) * TILE_WORDS;
    const uint32_t* srcH = g_btile + (size_t)(9 + chunk) * TILE_WORDS;
    for (int i = tid * 4; i < TILE_WORDS; i += 256 * 4) {
        cp_async16(sB + i * 4, srcI + i);
        cp_async16(sB + (TILE_WORDS + i) * 4, srcH + i);
    }
    CP_COMMIT();
}

__global__ void __launch_bounds__(256, 2)
fused_kernel(int layer, const float* __restrict__ bias_i, const float* __restrict__ bias_h)
{
    extern __shared__ uint32_t sm[];
    uint32_t* Ab = sm;
    uint32_t* Ah = sm + A_WORDS;
    uint32_t* Bi = sm + 2 * A_WORDS;
    uint32_t sBi = smem_to_u32(Bi);

    int tid = threadIdx.x;
    int rowBase = blockIdx.x * NROW;

    prefetch_chunk(sBi, layer, 0, tid);   // overlaps with A relayout

    // ---- A tiles: relayout fp16 hbar/h into padded smem ----
    for (int i = tid; i < NROW * 16; i += 256) {
        int row = i >> 4;
        int q4  = (i & 15) * 4;
        int grr = rowBase + row;
        uint4 vb = make_uint4(0u, 0u, 0u, 0u);
        uint4 vh = make_uint4(0u, 0u, 0u, 0u);
        if (grr < NN) {
            vb = *(const uint4*)(g_hbar16 + (size_t)grr * 64 + q4);
            vh = *(const uint4*)(g_h16   + (size_t)grr * 64 + q4);
        }
        int o = row * TSTR + q4;
        *(uint4*)(Ab + o) = vb;
        *(uint4*)(Ah + o) = vh;
    }

    int wid = tid >> 5, lane = tid & 31;
    int gr = lane >> 2, tig = lane & 3;
    int wm = wid >> 1, wn = wid & 1;

    // per-lane ldmatrix addresses (byte), ks=0
    int lg = lane >> 3, lr = lane & 7;
    uint32_t aOff = ((uint32_t)((wm * 16 + lr + (lg & 1) * 8) * TSTR + (lg >> 1) * 4)) * 4;
    uint32_t bOff = ((uint32_t)((wn * 64 + lr + (lg >> 1) * 8) * TSTR + (lg & 1) * 4)) * 4;
    uint32_t aAb = smem_to_u32(Ab) + aOff;
    uint32_t aAh = smem_to_u32(Ah) + aOff;
    uint32_t aBi = sBi + bOff;
    uint32_t aBh = sBi + TILE_WORDS * 4 + bOff;

    float rf[8][4], zf[8][4];

#pragma unroll
    for (int chunk = 0; chunk < 3; chunk++) {
        if (chunk > 0) {
            __syncthreads();                       // previous chunk's B readers done
            prefetch_chunk(sBi, layer, chunk, tid);
        }
        CP_WAIT0();
        __syncthreads();                           // B (and chunk0: A) visible

        if (chunk < 2) {
            float acc[8][4];
#pragma unroll
            for (int ni = 0; ni < 8; ni++)
#pragma unroll
                for (int q = 0; q < 4; q++) acc[ni][q] = 0.f;
            gemm_frag(aAb, aBi, acc);
            gemm_frag(aAh, aBh, acc);
#pragma unroll
            for (int ni = 0; ni < 8; ni++) {
                int cc = wn * 64 + ni * 8 + tig * 2;
#pragma unroll
                for (int q = 0; q < 4; q++) {
                    int col = chunk * 128 + cc + (q & 1);
                    float v = acc[ni][q] + bias_i[col] + bias_h[col];
                    float s = 1.0f / (1.0f + __expf(-v));
                    if (chunk == 0) rf[ni][q] = s; else zf[ni][q] = s;
                }
            }
        } else {
            // n = tanh(gi + b_i + r*(gh + b_h)) using ONE accumulator:
            // acc <- gh ; acc <- r*(acc+b_h) ; acc <- acc + gi (MMA) ; tanh(acc+b_i)
            float acc[8][4];
#pragma unroll
            for (int ni = 0; ni < 8; ni++)
#pragma unroll
                for (int q = 0; q < 4; q++) acc[ni][q] = 0.f;
            gemm_frag(aAh, aBh, acc);
#pragma unroll
            for (int ni = 0; ni < 8; ni++) {
                int cc = wn * 64 + ni * 8 + tig * 2;
                float bh0 = bias_h[256 + cc], bh1 = bias_h[256 + cc + 1];
                acc[ni][0] = rf[ni][0] * (acc[ni][0] + bh0);
                acc[ni][1] = rf[ni][1] * (acc[ni][1] + bh1);
                acc[ni][2] = rf[ni][2] * (acc[ni][2] + bh0);
                acc[ni][3] = rf[ni][3] * (acc[ni][3] + bh1);
            }
            gemm_frag(aAb, aBi, acc);

            int r0 = rowBase + wm * 16 + gr;
            int r1 = r0 + 8;
#pragma unroll
            for (int ni = 0; ni < 8; ni++) {
                int cc = wn * 64 + ni * 8 + tig * 2;
                float bi0 = bias_i[256 + cc], bi1 = bias_i[256 + cc + 1];
                if (r0 < NN) {
                    float2 ho = *(const float2*)(g_h + (size_t)r0 * C + cc);
                    float n0 = tanhf(acc[ni][0] + bi0);
                    float n1 = tanhf(acc[ni][1] + bi1);
                    float2 hn;
                    hn.x = (1.0f - zf[ni][0]) * n0 + zf[ni][0] * ho.x;
                    hn.y = (1.0f - zf[ni][1]) * n1 + zf[ni][1] * ho.y;
                    *(float2*)(g_h + (size_t)r0 * C + cc) = hn;
                    g_h16[(size_t)r0 * 64 + (cc >> 1)] = pack_h2(hn.x, hn.y);
                }
                if (r1 < NN) {
                    float2 ho = *(const float2*)(g_h + (size_t)r1 * C + cc);
                    float n2 = tanhf(acc[ni][2] + bi0);
                    float n3 = tanhf(acc[ni][3] + bi1);
                    float2 hn;
                    hn.x = (1.0f - zf[ni][2]) * n2 + zf[ni][2] * ho.x;
                    hn.y = (1.0f - zf[ni][3]) * n3 + zf[ni][3] * ho.y;
                    *(float2*)(g_h + (size_t)r1 * C + cc) = hn;
                    g_h16[(size_t)r1 * 64 + (cc >> 1)] = pack_h2(hn.x, hn.y);
                }
            }
        }
    }
}

// ================= final mean + tanh =================
__global__ void mean_tanh_kernel(float* __restrict__ out) {
    int gtid = blockIdx.x * blockDim.x + threadIdx.x;
    int node = gtid >> 5;
    int lane = threadIdx.x & 31;
    if (node < NN) {
        float4 v = *(const float4*)(g_h + (size_t)node * C + lane * 4);
        float s = v.x + v.y + v.z + v.w;
#pragma unroll
        for (int o = 16; o > 0; o >>= 1) s += __shfl_down_sync(0xffffffffu, s, o);
        if (lane == 0) out[node] = tanhf(s * (1.0f / 128.0f));
    }
}

// ================= launch =================
extern "C" void kernel_launch(void* const* d_in, const int* in_sizes, int n_in,
                              void* d_out, int out_size) {
    int ix = 0, ie = 1, iw = 2, iwih = 3, iwhh = 4, ibih = 5, ibhh = 6;
    {
        int w_seen = 0, b_seen = 0;
        for (int i = 0; i < n_in; i++) {
            long long s = in_sizes[i];
            if (s == (long long)NN * C) ix = i;
            else if (s == 2LL * NE) ie = i;
            else if (s == (long long)C3 * C) {
                if (w_seen == 0) iw = i;
                else if (w_seen == 1) iwih = i;
                else if (w_seen == 2) iwhh = i;
                w_seen++;
            } else if (s == C3) {
                if (b_seen == 0) ibih = i;
                else if (b_seen == 1) ibhh = i;
                b_seen++;
            }
        }
    }
    const float* x      = (const float*)d_in[ix];
    const void*  ei     = d_in[ie];
    const float* weight = (const float*)d_in[iw];
    const float* w_ih   = (const float*)d_in[iwih];
    const float* w_hh   = (const float*)d_in[iwhh];
    const float* b_ih   = (const float*)d_in[ibih];
    const float* b_hh   = (const float*)d_in[ibhh];
    float*       out    = (float*)d_out;

    static bool attr_set = false;
    if (!attr_set) {
        cudaFuncSetAttribute(fused_kernel, cudaFuncAttributeMaxDynamicSharedMemorySize, FUSED_SMEM);
        attr_set = true;
    }

    detect_kernel<<<1, 32>>>((const unsigned int*)ei);
    init_h_kernel<<<(NN * 64 + 255) / 256, 256>>>(x);
    zero_deg_kernel<<<(NN + 255) / 256, 256>>>();
    count_kernel<<<(NE + 255) / 256, 256>>>(ei);
    scanA_kernel<<<SCAN_NB, SCAN_B>>>();
    scanB_kernel<<<1, 32>>>();
    scanC_kernel<<<SCAN_NB, SCAN_B>>>();
    fill_kernel<<<(NE + 255) / 256, 256>>>(ei);
    wfused_kernel<<<(3 * 128 * 384 + 255) / 256, 256>>>(weight, w_ih);
    prep_btiles_kernel<<<(12 * 128 * 64 + 255) / 256, 256>>>(w_hh);

    int gather_blocks = (NN * 32 + 255) / 256;
    int fused_blocks = (NN + NROW - 1) / NROW;   // 1563

    for (int l = 0; l < NLAYERS; l++) {
        gather_kernel<<<gather_blocks, 256>>>();
        fused_kernel<<<fused_blocks, 256, FUSED_SMEM>>>(l, b_ih, b_hh);
    }

    mean_tanh_kernel<<<(NN * 32 + 255) / 256, 256>>>(out);
}

// round 12
// speedup vs baseline: 3.5985x; 1.1185x over previous
#include <cuda_runtime.h>
#include <cuda_fp16.h>
#include <cstdint>

#define NN 100000
#define NE 1600000
#define C 128
#define C3 384
#define NLAYERS 3
#define SCAN_B 512
#define SCAN_NB ((NN + SCAN_B - 1) / SCAN_B)   // 196

// padded tile layout: [rows][68 uint32 words] (64 used = 128 fp16, +4 pad)
#define TSTR 68
#define TILE_WORDS (128 * TSTR)       // B tiles: 128 n-rows  (34816 B)
#define NROW 64                       // fused-kernel CTA rows
#define A_WORDS (NROW * TSTR)         // A tiles: 64 rows     (17408 B)

// P1 role grid split
#define NB_COUNT 6250
#define NB_INIT  25000
#define NB_WF    576
// P2 role grid split
#define NB_FILL  6250
#define NB_PREPB 384

// ================= scratch (device globals; no allocation allowed) =================
__device__ __align__(256) float    g_h[NN * C];          // hidden state fp32
__device__ __align__(256) uint32_t g_h16[NN * 64];       // fp16 mirror of h
__device__ __align__(256) uint32_t g_hbar16[NN * 64];    // fp16 mean-pooled neighbor h
__device__ __align__(256) float    g_wfused[3 * 128 * 384];  // W_l @ w_ih^T (fp32)
// fp16 padded B tiles: 0-8 = Wfused (layer*3+chunk), 9-11 = w_hh chunks
__device__ __align__(256) uint32_t g_btile[12 * TILE_WORDS];
// CSR build
__device__ __align__(256) int g_deg[NN];
__device__ __align__(256) int g_bsum[SCAN_NB];
__device__ __align__(256) int g_rowptr[NN + 1];
__device__ __align__(256) int g_cur[NN];
__device__ __align__(256) int g_srclist[NE];

// ================= helpers =================
__device__ __forceinline__ uint32_t smem_to_u32(const void* p) {
    uint32_t a;
    asm("{ .reg .u64 t; cvta.to.shared.u64 t, %1; cvt.u32.u64 %0, t; }" : "=r"(a) : "l"(p));
    return a;
}
__device__ __forceinline__ void cp_async16(uint32_t saddr, const void* gaddr) {
    asm volatile("cp.async.cg.shared.global [%0], [%1], 16;" :: "r"(saddr), "l"(gaddr));
}
#define CP_COMMIT() asm volatile("cp.async.commit_group;" ::: "memory")
#define CP_WAIT0()  asm volatile("cp.async.wait_group 0;" ::: "memory")

__device__ __forceinline__ uint32_t pack_h2(float a, float b) {
    __half2 h = __floats2half2_rn(a, b);
    return *(uint32_t*)&h;
}
__device__ __forceinline__ void ldmx4(uint32_t* r, uint32_t saddr) {
    asm volatile("ldmatrix.sync.aligned.m8n8.x4.shared.b16 {%0,%1,%2,%3}, [%4];"
                 : "=r"(r[0]), "=r"(r[1]), "=r"(r[2]), "=r"(r[3]) : "r"(saddr));
}
__device__ __forceinline__ float tanh_ap(float x) {
    float y;
    asm("tanh.approx.f32 %0, %1;" : "=f"(y) : "f"(x));
    return y;
}
__device__ __forceinline__ float sigmoid_ap(float x) {
    return fmaf(tanh_ap(0.5f * x), 0.5f, 0.5f);
}

// per-block edge dtype detection (thread 0 + smem broadcast)
__device__ __forceinline__ int detect_block(const unsigned int* ei32, int* s_flag) {
    if (threadIdx.x == 0) {
        int is64 = 1;
        for (int i = 1; i < 64; i += 2)
            if (ei32[i] != 0u) { is64 = 0; break; }
        *s_flag = is64;
    }
    __syncthreads();
    return *s_flag;
}
__device__ __forceinline__ int load_edge_f(const void* ei, long long idx, int is64) {
    int v;
    if (is64) v = (int)((const long long*)ei)[idx];
    else      v = ((const int*)ei)[idx];
    return min(max(v, 0), NN - 1);
}

// ================= P0: zero degree array =================
__global__ void zero_deg_kernel() {
    int i = blockIdx.x * blockDim.x + threadIdx.x;
    if (i < NN) g_deg[i] = 0;
}

// ================= P1: count + init_h + wfused (independent roles, one grid) =====
__global__ void prep1_kernel(const void* __restrict__ ei, const float* __restrict__ x,
                             const float* __restrict__ weight, const float* __restrict__ w_ih) {
    __shared__ int s_flag;
    int b = blockIdx.x;
    if (b < NB_COUNT) {
        int is64 = detect_block((const unsigned int*)ei, &s_flag);
        int e = b * 256 + threadIdx.x;
        if (e < NE) atomicAdd(&g_deg[load_edge_f(ei, (long long)NE + e, is64)], 1);
    } else if (b < NB_COUNT + NB_INIT) {
        int i = (b - NB_COUNT) * 256 + threadIdx.x;
        if (i < NN * 64) {
            float2 v = ((const float2*)x)[i];
            ((float2*)g_h)[i] = v;
            g_h16[i] = pack_h2(v.x, v.y);
        }
    } else {
        int idx = (b - NB_COUNT - NB_INIT) * 256 + threadIdx.x;
        if (idx < 3 * 128 * 384) {
            int l = idx / 49152;
            int rem = idx % 49152;
            int k = rem / 384;
            int n = rem % 384;
            const float* wl = weight + l * 16384 + k * 128;
            const float* wr = w_ih + (size_t)n * 128;
            float s = 0.f;
#pragma unroll 8
            for (int j = 0; j < 128; j++) s += wl[j] * wr[j];
            g_wfused[idx] = s;
        }
    }
}

// ================= scans =================
__global__ void scanA_kernel() {
    __shared__ int sh[SCAN_B];
    int i = blockIdx.x * SCAN_B + threadIdx.x;
    sh[threadIdx.x] = (i < NN) ? g_deg[i] : 0;
    __syncthreads();
    for (int off = SCAN_B / 2; off > 0; off >>= 1) {
        if (threadIdx.x < off) sh[threadIdx.x] += sh[threadIdx.x + off];
        __syncthreads();
    }
    if (threadIdx.x == 0) g_bsum[blockIdx.x] = sh[0];
}
__global__ void scanB_kernel() {
    if (threadIdx.x == 0 && blockIdx.x == 0) {
        int run = 0;
        for (int b = 0; b < SCAN_NB; b++) { int v = g_bsum[b]; g_bsum[b] = run; run += v; }
    }
}
__global__ void scanC_kernel() {
    __shared__ int sh[SCAN_B];
    int i = blockIdx.x * SCAN_B + threadIdx.x;
    int v = (i < NN) ? g_deg[i] : 0;
    sh[threadIdx.x] = v;
    __syncthreads();
    for (int off = 1; off < SCAN_B; off <<= 1) {
        int t = (threadIdx.x >= off) ? sh[threadIdx.x - off] : 0;
        __syncthreads();
        sh[threadIdx.x] += t;
        __syncthreads();
    }
    if (i < NN) {
        int excl = sh[threadIdx.x] - v + g_bsum[blockIdx.x];
        g_rowptr[i] = excl;
        g_cur[i] = excl;
    }
    if (i == NN - 1) g_rowptr[NN] = NE;
}

// ================= P2: fill + prep_btiles (one grid) =================
__global__ void prep2_kernel(const void* __restrict__ ei, const float* __restrict__ w_hh) {
    __shared__ int s_flag;
    int b = blockIdx.x;
    if (b < NB_FILL) {
        int is64 = detect_block((const unsigned int*)ei, &s_flag);
        int e = b * 256 + threadIdx.x;
        if (e < NE) {
            int src = load_edge_f(ei, e, is64);
            int dst = load_edge_f(ei, (long long)NE + e, is64);
            int pos = atomicAdd(&g_cur[dst], 1);
            if (pos >= 0 && pos < NE) g_srclist[pos] = src;
        }
    } else {
        int idx = (b - NB_FILL) * 256 + threadIdx.x;
        if (idx < 12 * 128 * 64) {
            int tile = idx >> 13;
            int rem  = idx & 8191;
            int n  = rem >> 6;
            int k2 = rem & 63;
            float v0, v1;
            if (tile < 9) {
                int l = tile / 3, chunk = tile % 3;
                const float* base = g_wfused + l * 49152 + chunk * 128 + n;
                v0 = base[(k2 * 2) * 384];
                v1 = base[(k2 * 2 + 1) * 384];
            } else {
                const float* r = w_hh + ((size_t)((tile - 9) * 128 + n)) * 128;
                v0 = r[k2 * 2];  v1 = r[k2 * 2 + 1];
            }
            g_btile[(size_t)tile * TILE_WORDS + n * TSTR + k2] = pack_h2(v0, v1);
        }
    }
}

// ================= gather: hbar16 = mean of h16 over in-neighbors =================
__global__ void gather_kernel() {
    int warp = (blockIdx.x * blockDim.x + threadIdx.x) >> 5;
    int lane = threadIdx.x & 31;
    if (warp >= NN) return;
    int s = g_rowptr[warp];
    int e = g_rowptr[warp + 1];
    float4 acc = make_float4(0.f, 0.f, 0.f, 0.f);
    int i = s;
    for (; i + 4 <= e; i += 4) {
        int s0 = g_srclist[i],     s1 = g_srclist[i + 1];
        int s2 = g_srclist[i + 2], s3 = g_srclist[i + 3];
        uint2 w0 = *(const uint2*)(g_h16 + (size_t)s0 * 64 + lane * 2);
        uint2 w1 = *(const uint2*)(g_h16 + (size_t)s1 * 64 + lane * 2);
        uint2 w2 = *(const uint2*)(g_h16 + (size_t)s2 * 64 + lane * 2);
        uint2 w3 = *(const uint2*)(g_h16 + (size_t)s3 * 64 + lane * 2);
        float2 a0 = __half22float2(*(__half2*)&w0.x), a1 = __half22float2(*(__half2*)&w0.y);
        float2 b0 = __half22float2(*(__half2*)&w1.x), b1 = __half22float2(*(__half2*)&w1.y);
        float2 c0 = __half22float2(*(__half2*)&w2.x), c1 = __half22float2(*(__half2*)&w2.y);
        float2 d0 = __half22float2(*(__half2*)&w3.x), d1 = __half22float2(*(__half2*)&w3.y);
        acc.x += (a0.x + b0.x) + (c0.x + d0.x);
        acc.y += (a0.y + b0.y) + (c0.y + d0.y);
        acc.z += (a1.x + b1.x) + (c1.x + d1.x);
        acc.w += (a1.y + b1.y) + (c1.y + d1.y);
    }
    for (; i < e; i++) {
        int s0 = g_srclist[i];
        uint2 w0 = *(const uint2*)(g_h16 + (size_t)s0 * 64 + lane * 2);
        float2 a0 = __half22float2(*(__half2*)&w0.x), a1 = __half22float2(*(__half2*)&w0.y);
        acc.x += a0.x;  acc.y += a0.y;  acc.z += a1.x;  acc.w += a1.y;
    }
    float sc = 1.0f / fmaxf((float)(e - s), 1.0f);
    uint2 outw;
    outw.x = pack_h2(acc.x * sc, acc.y * sc);
    outw.y = pack_h2(acc.z * sc, acc.w * sc);
    *(uint2*)(g_hbar16 + (size_t)warp * 64 + lane * 2) = outw;
}

// ================= mma.sync m16n8k16 fp16 =================
__device__ __forceinline__ void mma16816(float* c, const uint32_t* a, const uint32_t* b) {
    asm volatile(
        "mma.sync.aligned.m16n8k16.row.col.f32.f16.f16.f32 "
        "{%0,%1,%2,%3}, {%4,%5,%6,%7}, {%8,%9}, {%0,%1,%2,%3};"
        : "+f"(c[0]), "+f"(c[1]), "+f"(c[2]), "+f"(c[3])
        : "r"(a[0]), "r"(a[1]), "r"(a[2]), "r"(a[3]), "r"(b[0]), "r"(b[1]));
}

__device__ __forceinline__ void gemm_frag(uint32_t aAddr, uint32_t bAddr, float acc[8][4]) {
#pragma unroll
    for (int ks = 0; ks < 8; ks++) {
        uint32_t a[4];
        ldmx4(a, aAddr + ks * 32);
#pragma unroll
        for (int p = 0; p < 4; p++) {
            uint32_t b[4];
            ldmx4(b, bAddr + p * (16 * TSTR * 4) + ks * 32);
            mma16816(acc[2 * p],     a, b);
            mma16816(acc[2 * p + 1], a, b + 2);
        }
    }
}

// ================= fused gi-GEMM + gh-GEMM + GRU gate =================
#define FUSED_SMEM ((2 * A_WORDS + 2 * TILE_WORDS) * 4)   // 104448 B, 2 CTAs/SM

__device__ __forceinline__ void prefetch_chunk(uint32_t sB, int layer, int chunk, int tid) {
    const uint32_t* srcI = g_btile + (size_t)(layer * 3 + chunk) * TILE_WORDS;
    const uint32_t* srcH = g_btile + (size_t)(9 + chunk) * TILE_WORDS;
    for (int i = tid * 4; i < TILE_WORDS; i += 256 * 4) {
        cp_async16(sB + i * 4, srcI + i);
        cp_async16(sB + (TILE_WORDS + i) * 4, srcH + i);
    }
    CP_COMMIT();
}

__global__ void __launch_bounds__(256, 2)
fused_kernel(int layer, const float* __restrict__ bias_i, const float* __restrict__ bias_h)
{
    extern __shared__ uint32_t sm[];
    uint32_t* Ab = sm;
    uint32_t* Ah = sm + A_WORDS;
    uint32_t* Bi = sm + 2 * A_WORDS;
    uint32_t sBi = smem_to_u32(Bi);

    int tid = threadIdx.x;
    int rowBase = blockIdx.x * NROW;

    prefetch_chunk(sBi, layer, 0, tid);   // overlaps with A relayout

    for (int i = tid; i < NROW * 16; i += 256) {
        int row = i >> 4;
        int q4  = (i & 15) * 4;
        int grr = rowBase + row;
        uint4 vb = make_uint4(0u, 0u, 0u, 0u);
        uint4 vh = make_uint4(0u, 0u, 0u, 0u);
        if (grr < NN) {
            vb = *(const uint4*)(g_hbar16 + (size_t)grr * 64 + q4);
            vh = *(const uint4*)(g_h16   + (size_t)grr * 64 + q4);
        }
        int o = row * TSTR + q4;
        *(uint4*)(Ab + o) = vb;
        *(uint4*)(Ah + o) = vh;
    }

    int wid = tid >> 5, lane = tid & 31;
    int gr = lane >> 2, tig = lane & 3;
    int wm = wid >> 1, wn = wid & 1;

    int lg = lane >> 3, lr = lane & 7;
    uint32_t aOff = ((uint32_t)((wm * 16 + lr + (lg & 1) * 8) * TSTR + (lg >> 1) * 4)) * 4;
    uint32_t bOff = ((uint32_t)((wn * 64 + lr + (lg >> 1) * 8) * TSTR + (lg & 1) * 4)) * 4;
    uint32_t aAb = smem_to_u32(Ab) + aOff;
    uint32_t aAh = smem_to_u32(Ah) + aOff;
    uint32_t aBi = sBi + bOff;
    uint32_t aBh = sBi + TILE_WORDS * 4 + bOff;

    float rf[8][4], zf[8][4];

#pragma unroll
    for (int chunk = 0; chunk < 3; chunk++) {
        if (chunk > 0) {
            __syncthreads();                       // previous chunk's B readers done
            prefetch_chunk(sBi, layer, chunk, tid);
        }
        CP_WAIT0();
        __syncthreads();                           // B (and chunk0: A) visible

        if (chunk < 2) {
            float acc[8][4];
#pragma unroll
            for (int ni = 0; ni < 8; ni++)
#pragma unroll
                for (int q = 0; q < 4; q++) acc[ni][q] = 0.f;
            gemm_frag(aAb, aBi, acc);
            gemm_frag(aAh, aBh, acc);
#pragma unroll
            for (int ni = 0; ni < 8; ni++) {
                int cc = wn * 64 + ni * 8 + tig * 2;
#pragma unroll
                for (int q = 0; q < 4; q++) {
                    int col = chunk * 128 + cc + (q & 1);
                    float v = acc[ni][q] + bias_i[col] + bias_h[col];
                    float s = sigmoid_ap(v);
                    if (chunk == 0) rf[ni][q] = s; else zf[ni][q] = s;
                }
            }
        } else {
            // n = tanh(gi + b_i + r*(gh + b_h)) with ONE accumulator
            float acc[8][4];
#pragma unroll
            for (int ni = 0; ni < 8; ni++)
#pragma unroll
                for (int q = 0; q < 4; q++) acc[ni][q] = 0.f;
            gemm_frag(aAh, aBh, acc);
#pragma unroll
            for (int ni = 0; ni < 8; ni++) {
                int cc = wn * 64 + ni * 8 + tig * 2;
                float bh0 = bias_h[256 + cc], bh1 = bias_h[256 + cc + 1];
                acc[ni][0] = rf[ni][0] * (acc[ni][0] + bh0);
                acc[ni][1] = rf[ni][1] * (acc[ni][1] + bh1);
                acc[ni][2] = rf[ni][2] * (acc[ni][2] + bh0);
                acc[ni][3] = rf[ni][3] * (acc[ni][3] + bh1);
            }
            gemm_frag(aAb, aBi, acc);

            int r0 = rowBase + wm * 16 + gr;
            int r1 = r0 + 8;
#pragma unroll
            for (int ni = 0; ni < 8; ni++) {
                int cc = wn * 64 + ni * 8 + tig * 2;
                float bi0 = bias_i[256 + cc], bi1 = bias_i[256 + cc + 1];
                if (r0 < NN) {
                    float2 ho = *(const float2*)(g_h + (size_t)r0 * C + cc);
                    float n0 = tanh_ap(acc[ni][0] + bi0);
                    float n1 = tanh_ap(acc[ni][1] + bi1);
                    float2 hn;
                    hn.x = (1.0f - zf[ni][0]) * n0 + zf[ni][0] * ho.x;
                    hn.y = (1.0f - zf[ni][1]) * n1 + zf[ni][1] * ho.y;
                    *(float2*)(g_h + (size_t)r0 * C + cc) = hn;
                    g_h16[(size_t)r0 * 64 + (cc >> 1)] = pack_h2(hn.x, hn.y);
                }
                if (r1 < NN) {
                    float2 ho = *(const float2*)(g_h + (size_t)r1 * C + cc);
                    float n2 = tanh_ap(acc[ni][2] + bi0);
                    float n3 = tanh_ap(acc[ni][3] + bi1);
                    float2 hn;
                    hn.x = (1.0f - zf[ni][2]) * n2 + zf[ni][2] * ho.x;
                    hn.y = (1.0f - zf[ni][3]) * n3 + zf[ni][3] * ho.y;
                    *(float2*)(g_h + (size_t)r1 * C + cc) = hn;
                    g_h16[(size_t)r1 * 64 + (cc >> 1)] = pack_h2(hn.x, hn.y);
                }
            }
        }
    }
}

// ================= final mean + tanh (precise tanhf; only 100k values) =============
__global__ void mean_tanh_kernel(float* __restrict__ out) {
    int gtid = blockIdx.x * blockDim.x + threadIdx.x;
    int node = gtid >> 5;
    int lane = threadIdx.x & 31;
    if (node < NN) {
        float4 v = *(const float4*)(g_h + (size_t)node * C + lane * 4);
        float s = v.x + v.y + v.z + v.w;
#pragma unroll
        for (int o = 16; o > 0; o >>= 1) s += __shfl_down_sync(0xffffffffu, s, o);
        if (lane == 0) out[node] = tanhf(s * (1.0f / 128.0f));
    }
}

// ================= launch =================
extern "C" void kernel_launch(void* const* d_in, const int* in_sizes, int n_in,
                              void* d_out, int out_size) {
    int ix = 0, ie = 1, iw = 2, iwih = 3, iwhh = 4, ibih = 5, ibhh = 6;
    {
        int w_seen = 0, b_seen = 0;
        for (int i = 0; i < n_in; i++) {
            long long s = in_sizes[i];
            if (s == (long long)NN * C) ix = i;
            else if (s == 2LL * NE) ie = i;
            else if (s == (long long)C3 * C) {
                if (w_seen == 0) iw = i;
                else if (w_seen == 1) iwih = i;
                else if (w_seen == 2) iwhh = i;
                w_seen++;
            } else if (s == C3) {
                if (b_seen == 0) ibih = i;
                else if (b_seen == 1) ibhh = i;
                b_seen++;
            }
        }
    }
    const float* x      = (const float*)d_in[ix];
    const void*  ei     = d_in[ie];
    const float* weight = (const float*)d_in[iw];
    const float* w_ih   = (const float*)d_in[iwih];
    const float* w_hh   = (const float*)d_in[iwhh];
    const float* b_ih   = (const float*)d_in[ibih];
    const float* b_hh   = (const float*)d_in[ibhh];
    float*       out    = (float*)d_out;

    static bool attr_set = false;
    if (!attr_set) {
        cudaFuncSetAttribute(fused_kernel, cudaFuncAttributeMaxDynamicSharedMemorySize, FUSED_SMEM);
        attr_set = true;
    }

    zero_deg_kernel<<<(NN + 255) / 256, 256>>>();
    prep1_kernel<<<NB_COUNT + NB_INIT + NB_WF, 256>>>(ei, x, weight, w_ih);
    scanA_kernel<<<SCAN_NB, SCAN_B>>>();
    scanB_kernel<<<1, 32>>>();
    scanC_kernel<<<SCAN_NB, SCAN_B>>>();
    prep2_kernel<<<NB_FILL + NB_PREPB, 256>>>(ei, w_hh);

    int gather_blocks = (NN * 32 + 255) / 256;
    int fused_blocks = (NN + NROW - 1) / NROW;   // 1563

    for (int l = 0; l < NLAYERS; l++) {
        gather_kernel<<<gather_blocks, 256>>>();
        fused_kernel<<<fused_blocks, 256, FUSED_SMEM>>>(l, b_ih, b_hh);
    }

    mean_tanh_kernel<<<(NN * 32 + 255) / 256, 256>>>(out);
}

// round 13
// speedup vs baseline: 4.1440x; 1.1516x over previous
#include <cuda_runtime.h>
#include <cuda_fp16.h>
#include <cstdint>

#define NN 100000
#define NE 1600000
#define C 128
#define C3 384
#define NLAYERS 3
#define SCAN_B 512
#define SCAN_NB ((NN + SCAN_B - 1) / SCAN_B)   // 196

// padded tile layout: [rows][68 uint32 words] (64 used = 128 fp16, +4 pad)
#define TSTR 68
#define TILE_WORDS (128 * TSTR)       // B tiles: 128 n-rows  (34816 B)
#define NROW 64                       // fused-kernel CTA rows
#define A_WORDS (NROW * TSTR)         // A tiles: 64 rows     (17408 B)

// P1 role grid split
#define NB_COUNT 6250
#define NB_INIT  25000
#define NB_WF    576
// P2 role grid split
#define NB_FILL  6250
#define NB_PREPB 384

// ================= scratch (device globals; no allocation allowed) =================
__device__ __align__(256) uint32_t g_h16[NN * 64];       // hidden state (fp16 half2 words)
__device__ __align__(256) uint32_t g_hbar16[NN * 64];    // fp16 mean-pooled neighbor h
__device__ __align__(256) float    g_wfused[3 * 128 * 384];  // W_l @ w_ih^T (fp32)
// fp16 padded B tiles: 0-8 = Wfused (layer*3+chunk), 9-11 = w_hh chunks
__device__ __align__(256) uint32_t g_btile[12 * TILE_WORDS];
// CSR build
__device__ __align__(256) int g_deg[NN];
__device__ __align__(256) int g_bsum[SCAN_NB];
__device__ __align__(256) int g_rowptr[NN + 1];
__device__ __align__(256) int g_cur[NN];
__device__ __align__(256) int g_srclist[NE];

// ================= helpers =================
__device__ __forceinline__ uint32_t smem_to_u32(const void* p) {
    uint32_t a;
    asm("{ .reg .u64 t; cvta.to.shared.u64 t, %1; cvt.u32.u64 %0, t; }" : "=r"(a) : "l"(p));
    return a;
}
__device__ __forceinline__ void cp_async16(uint32_t saddr, const void* gaddr) {
    asm volatile("cp.async.cg.shared.global [%0], [%1], 16;" :: "r"(saddr), "l"(gaddr));
}
#define CP_COMMIT() asm volatile("cp.async.commit_group;" ::: "memory")
#define CP_WAIT0()  asm volatile("cp.async.wait_group 0;" ::: "memory")

__device__ __forceinline__ uint32_t pack_h2(float a, float b) {
    __half2 h = __floats2half2_rn(a, b);
    return *(uint32_t*)&h;
}
__device__ __forceinline__ void ldmx4(uint32_t* r, uint32_t saddr) {
    asm volatile("ldmatrix.sync.aligned.m8n8.x4.shared.b16 {%0,%1,%2,%3}, [%4];"
                 : "=r"(r[0]), "=r"(r[1]), "=r"(r[2]), "=r"(r[3]) : "r"(saddr));
}
__device__ __forceinline__ float tanh_ap(float x) {
    float y;
    asm("tanh.approx.f32 %0, %1;" : "=f"(y) : "f"(x));
    return y;
}
__device__ __forceinline__ float sigmoid_ap(float x) {
    return fmaf(tanh_ap(0.5f * x), 0.5f, 0.5f);
}

// per-block edge dtype detection (thread 0 + smem broadcast)
__device__ __forceinline__ int detect_block(const unsigned int* ei32, int* s_flag) {
    if (threadIdx.x == 0) {
        int is64 = 1;
        for (int i = 1; i < 64; i += 2)
            if (ei32[i] != 0u) { is64 = 0; break; }
        *s_flag = is64;
    }
    __syncthreads();
    return *s_flag;
}
__device__ __forceinline__ int load_edge_f(const void* ei, long long idx, int is64) {
    int v;
    if (is64) v = (int)((const long long*)ei)[idx];
    else      v = ((const int*)ei)[idx];
    return min(max(v, 0), NN - 1);
}

// ================= P0: zero degree array =================
__global__ void zero_deg_kernel() {
    int i = blockIdx.x * blockDim.x + threadIdx.x;
    if (i < NN) g_deg[i] = 0;
}

// ================= P1: count + init_h + wfused (one grid, role by block) =========
__global__ void prep1_kernel(const void* __restrict__ ei, const float* __restrict__ x,
                             const float* __restrict__ weight, const float* __restrict__ w_ih) {
    __shared__ int s_flag;
    int b = blockIdx.x;
    if (b < NB_COUNT) {
        int is64 = detect_block((const unsigned int*)ei, &s_flag);
        int e = b * 256 + threadIdx.x;
        if (e < NE) atomicAdd(&g_deg[load_edge_f(ei, (long long)NE + e, is64)], 1);
    } else if (b < NB_COUNT + NB_INIT) {
        int i = (b - NB_COUNT) * 256 + threadIdx.x;
        if (i < NN * 64) {
            float2 v = ((const float2*)x)[i];
            g_h16[i] = pack_h2(v.x, v.y);
        }
    } else {
        int idx = (b - NB_COUNT - NB_INIT) * 256 + threadIdx.x;
        if (idx < 3 * 128 * 384) {
            int l = idx / 49152;
            int rem = idx % 49152;
            int k = rem / 384;
            int n = rem % 384;
            const float* wl = weight + l * 16384 + k * 128;
            const float* wr = w_ih + (size_t)n * 128;
            float s = 0.f;
#pragma unroll 8
            for (int j = 0; j < 128; j++) s += wl[j] * wr[j];
            g_wfused[idx] = s;
        }
    }
}

// ================= scans =================
__global__ void scanA_kernel() {
    __shared__ int sh[SCAN_B];
    int i = blockIdx.x * SCAN_B + threadIdx.x;
    sh[threadIdx.x] = (i < NN) ? g_deg[i] : 0;
    __syncthreads();
    for (int off = SCAN_B / 2; off > 0; off >>= 1) {
        if (threadIdx.x < off) sh[threadIdx.x] += sh[threadIdx.x + off];
        __syncthreads();
    }
    if (threadIdx.x == 0) g_bsum[blockIdx.x] = sh[0];
}
__global__ void scanB_kernel() {
    if (threadIdx.x == 0 && blockIdx.x == 0) {
        int run = 0;
        for (int b = 0; b < SCAN_NB; b++) { int v = g_bsum[b]; g_bsum[b] = run; run += v; }
    }
}
__global__ void scanC_kernel() {
    __shared__ int sh[SCAN_B];
    int i = blockIdx.x * SCAN_B + threadIdx.x;
    int v = (i < NN) ? g_deg[i] : 0;
    sh[threadIdx.x] = v;
    __syncthreads();
    for (int off = 1; off < SCAN_B; off <<= 1) {
        int t = (threadIdx.x >= off) ? sh[threadIdx.x - off] : 0;
        __syncthreads();
        sh[threadIdx.x] += t;
        __syncthreads();
    }
    if (i < NN) {
        int excl = sh[threadIdx.x] - v + g_bsum[blockIdx.x];
        g_rowptr[i] = excl;
        g_cur[i] = excl;
    }
    if (i == NN - 1) g_rowptr[NN] = NE;
}

// ================= P2: fill + prep_btiles (one grid) =================
__global__ void prep2_kernel(const void* __restrict__ ei, const float* __restrict__ w_hh) {
    __shared__ int s_flag;
    int b = blockIdx.x;
    if (b < NB_FILL) {
        int is64 = detect_block((const unsigned int*)ei, &s_flag);
        int e = b * 256 + threadIdx.x;
        if (e < NE) {
            int src = load_edge_f(ei, e, is64);
            int dst = load_edge_f(ei, (long long)NE + e, is64);
            int pos = atomicAdd(&g_cur[dst], 1);
            if (pos >= 0 && pos < NE) g_srclist[pos] = src;
        }
    } else {
        int idx = (b - NB_FILL) * 256 + threadIdx.x;
        if (idx < 12 * 128 * 64) {
            int tile = idx >> 13;
            int rem  = idx & 8191;
            int n  = rem >> 6;
            int k2 = rem & 63;
            float v0, v1;
            if (tile < 9) {
                int l = tile / 3, chunk = tile % 3;
                const float* base = g_wfused + l * 49152 + chunk * 128 + n;
                v0 = base[(k2 * 2) * 384];
                v1 = base[(k2 * 2 + 1) * 384];
            } else {
                const float* r = w_hh + ((size_t)((tile - 9) * 128 + n)) * 128;
                v0 = r[k2 * 2];  v1 = r[k2 * 2 + 1];
            }
            g_btile[(size_t)tile * TILE_WORDS + n * TSTR + k2] = pack_h2(v0, v1);
        }
    }
}

// ================= gather: hbar16 = mean of h16 over in-neighbors =================
__global__ void gather_kernel() {
    int warp = (blockIdx.x * blockDim.x + threadIdx.x) >> 5;
    int lane = threadIdx.x & 31;
    if (warp >= NN) return;
    int s = g_rowptr[warp];
    int e = g_rowptr[warp + 1];
    float4 acc = make_float4(0.f, 0.f, 0.f, 0.f);
    int i = s;
    for (; i + 4 <= e; i += 4) {
        int s0 = g_srclist[i],     s1 = g_srclist[i + 1];
        int s2 = g_srclist[i + 2], s3 = g_srclist[i + 3];
        uint2 w0 = *(const uint2*)(g_h16 + (size_t)s0 * 64 + lane * 2);
        uint2 w1 = *(const uint2*)(g_h16 + (size_t)s1 * 64 + lane * 2);
        uint2 w2 = *(const uint2*)(g_h16 + (size_t)s2 * 64 + lane * 2);
        uint2 w3 = *(const uint2*)(g_h16 + (size_t)s3 * 64 + lane * 2);
        float2 a0 = __half22float2(*(__half2*)&w0.x), a1 = __half22float2(*(__half2*)&w0.y);
        float2 b0 = __half22float2(*(__half2*)&w1.x), b1 = __half22float2(*(__half2*)&w1.y);
        float2 c0 = __half22float2(*(__half2*)&w2.x), c1 = __half22float2(*(__half2*)&w2.y);
        float2 d0 = __half22float2(*(__half2*)&w3.x), d1 = __half22float2(*(__half2*)&w3.y);
        acc.x += (a0.x + b0.x) + (c0.x + d0.x);
        acc.y += (a0.y + b0.y) + (c0.y + d0.y);
        acc.z += (a1.x + b1.x) + (c1.x + d1.x);
        acc.w += (a1.y + b1.y) + (c1.y + d1.y);
    }
    for (; i < e; i++) {
        int s0 = g_srclist[i];
        uint2 w0 = *(const uint2*)(g_h16 + (size_t)s0 * 64 + lane * 2);
        float2 a0 = __half22float2(*(__half2*)&w0.x), a1 = __half22float2(*(__half2*)&w0.y);
        acc.x += a0.x;  acc.y += a0.y;  acc.z += a1.x;  acc.w += a1.y;
    }
    float sc = 1.0f / fmaxf((float)(e - s), 1.0f);
    uint2 outw;
    outw.x = pack_h2(acc.x * sc, acc.y * sc);
    outw.y = pack_h2(acc.z * sc, acc.w * sc);
    *(uint2*)(g_hbar16 + (size_t)warp * 64 + lane * 2) = outw;
}

// ================= mma.sync m16n8k16 fp16 =================
__device__ __forceinline__ void mma16816(float* c, const uint32_t* a, const uint32_t* b) {
    asm volatile(
        "mma.sync.aligned.m16n8k16.row.col.f32.f16.f16.f32 "
        "{%0,%1,%2,%3}, {%4,%5,%6,%7}, {%8,%9}, {%0,%1,%2,%3};"
        : "+f"(c[0]), "+f"(c[1]), "+f"(c[2]), "+f"(c[3])
        : "r"(a[0]), "r"(a[1]), "r"(a[2]), "r"(a[3]), "r"(b[0]), "r"(b[1]));
}

__device__ __forceinline__ void gemm_frag(uint32_t aAddr, uint32_t bAddr, float acc[8][4]) {
#pragma unroll
    for (int ks = 0; ks < 8; ks++) {
        uint32_t a[4];
        ldmx4(a, aAddr + ks * 32);
#pragma unroll
        for (int p = 0; p < 4; p++) {
            uint32_t b[4];
            ldmx4(b, bAddr + p * (16 * TSTR * 4) + ks * 32);
            mma16816(acc[2 * p],     a, b);
            mma16816(acc[2 * p + 1], a, b + 2);
        }
    }
}

// ================= fused gi-GEMM + gh-GEMM + GRU gate =================
#define FUSED_SMEM ((2 * A_WORDS + 2 * TILE_WORDS) * 4)   // 104448 B, 2 CTAs/SM

__device__ __forceinline__ void prefetch_chunk(uint32_t sB, int layer, int chunk, int tid) {
    const uint32_t* srcI = g_btile + (size_t)(layer * 3 + chunk) * TILE_WORDS;
    const uint32_t* srcH = g_btile + (size_t)(9 + chunk) * TILE_WORDS;
    for (int i = tid * 4; i < TILE_WORDS; i += 256 * 4) {
        cp_async16(sB + i * 4, srcI + i);
        cp_async16(sB + (TILE_WORDS + i) * 4, srcH + i);
    }
    CP_COMMIT();
}

__global__ void __launch_bounds__(256, 2)
fused_kernel(int layer, const float* __restrict__ bias_i, const float* __restrict__ bias_h)
{
    extern __shared__ uint32_t sm[];
    uint32_t* Ab = sm;
    uint32_t* Ah = sm + A_WORDS;
    uint32_t* Bi = sm + 2 * A_WORDS;
    uint32_t sBi = smem_to_u32(Bi);

    int tid = threadIdx.x;
    int rowBase = blockIdx.x * NROW;

    prefetch_chunk(sBi, layer, 0, tid);   // overlaps with A relayout

    // ---- A tiles: relayout fp16 hbar/h into padded smem ----
    for (int i = tid; i < NROW * 16; i += 256) {
        int row = i >> 4;
        int q4  = (i & 15) * 4;
        int grr = rowBase + row;
        uint4 vb = make_uint4(0u, 0u, 0u, 0u);
        uint4 vh = make_uint4(0u, 0u, 0u, 0u);
        if (grr < NN) {
            vb = *(const uint4*)(g_hbar16 + (size_t)grr * 64 + q4);
            vh = *(const uint4*)(g_h16   + (size_t)grr * 64 + q4);
        }
        int o = row * TSTR + q4;
        *(uint4*)(Ab + o) = vb;
        *(uint4*)(Ah + o) = vh;
    }

    int wid = tid >> 5, lane = tid & 31;
    int gr = lane >> 2, tig = lane & 3;
    int wm = wid >> 1, wn = wid & 1;

    int lg = lane >> 3, lr = lane & 7;
    uint32_t aOff = ((uint32_t)((wm * 16 + lr + (lg & 1) * 8) * TSTR + (lg >> 1) * 4)) * 4;
    uint32_t bOff = ((uint32_t)((wn * 64 + lr + (lg >> 1) * 8) * TSTR + (lg & 1) * 4)) * 4;
    uint32_t aAb = smem_to_u32(Ab) + aOff;
    uint32_t aAh = smem_to_u32(Ah) + aOff;
    uint32_t aBi = sBi + bOff;
    uint32_t aBh = sBi + TILE_WORDS * 4 + bOff;

    float rf[8][4], zf[8][4];

#pragma unroll
    for (int chunk = 0; chunk < 3; chunk++) {
        CP_WAIT0();
        __syncthreads();   // B chunk (and chunk0: A tiles) visible to all warps

        if (chunk < 2) {
            float acc[8][4];
#pragma unroll
            for (int ni = 0; ni < 8; ni++)
#pragma unroll
                for (int q = 0; q < 4; q++) acc[ni][q] = 0.f;
            gemm_frag(aAb, aBi, acc);
            gemm_frag(aAh, aBh, acc);

            __syncthreads();                       // all warps done reading B
            prefetch_chunk(sBi, layer, chunk + 1, tid);   // overlaps epilogue below

#pragma unroll
            for (int ni = 0; ni < 8; ni++) {
                int cc = wn * 64 + ni * 8 + tig * 2;
#pragma unroll
                for (int q = 0; q < 4; q++) {
                    int col = chunk * 128 + cc + (q & 1);
                    float v = acc[ni][q] + bias_i[col] + bias_h[col];
                    float s = sigmoid_ap(v);
                    if (chunk == 0) rf[ni][q] = s; else zf[ni][q] = s;
                }
            }
        } else {
            // n = tanh(gi + b_i + r*(gh + b_h)) with ONE accumulator
            float acc[8][4];
#pragma unroll
            for (int ni = 0; ni < 8; ni++)
#pragma unroll
                for (int q = 0; q < 4; q++) acc[ni][q] = 0.f;
            gemm_frag(aAh, aBh, acc);
#pragma unroll
            for (int ni = 0; ni < 8; ni++) {
                int cc = wn * 64 + ni * 8 + tig * 2;
                float bh0 = bias_h[256 + cc], bh1 = bias_h[256 + cc + 1];
                acc[ni][0] = rf[ni][0] * (acc[ni][0] + bh0);
                acc[ni][1] = rf[ni][1] * (acc[ni][1] + bh1);
                acc[ni][2] = rf[ni][2] * (acc[ni][2] + bh0);
                acc[ni][3] = rf[ni][3] * (acc[ni][3] + bh1);
            }
            gemm_frag(aAb, aBi, acc);

            int lr0 = wm * 16 + gr;               // local rows
            int r0 = rowBase + lr0;
            int r1 = r0 + 8;
#pragma unroll
            for (int ni = 0; ni < 8; ni++) {
                int cc = wn * 64 + ni * 8 + tig * 2;
                int hw = cc >> 1;                  // half2 word index
                float bi0 = bias_i[256 + cc], bi1 = bias_i[256 + cc + 1];
                if (r0 < NN) {
                    float2 ho = __half22float2(*(__half2*)&Ah[lr0 * TSTR + hw]);
                    float n0 = tanh_ap(acc[ni][0] + bi0);
                    float n1 = tanh_ap(acc[ni][1] + bi1);
                    float hx = (1.0f - zf[ni][0]) * n0 + zf[ni][0] * ho.x;
                    float hy = (1.0f - zf[ni][1]) * n1 + zf[ni][1] * ho.y;
                    g_h16[(size_t)r0 * 64 + hw] = pack_h2(hx, hy);
                }
                if (r1 < NN) {
                    float2 ho = __half22float2(*(__half2*)&Ah[(lr0 + 8) * TSTR + hw]);
                    float n2 = tanh_ap(acc[ni][2] + bi0);
                    float n3 = tanh_ap(acc[ni][3] + bi1);
                    float hx = (1.0f - zf[ni][2]) * n2 + zf[ni][2] * ho.x;
                    float hy = (1.0f - zf[ni][3]) * n3 + zf[ni][3] * ho.y;
                    g_h16[(size_t)r1 * 64 + hw] = pack_h2(hx, hy);
                }
            }
        }
    }
}

// ================= final mean + tanh (reads h16) =================
__global__ void mean_tanh_kernel(float* __restrict__ out) {
    int gtid = blockIdx.x * blockDim.x + threadIdx.x;
    int node = gtid >> 5;
    int lane = threadIdx.x & 31;
    if (node < NN) {
        uint2 w = *(const uint2*)(g_h16 + (size_t)node * 64 + lane * 2);
        float2 a = __half22float2(*(__half2*)&w.x);
        float2 b = __half22float2(*(__half2*)&w.y);
        float s = (a.x + a.y) + (b.x + b.y);
#pragma unroll
        for (int o = 16; o > 0; o >>= 1) s += __shfl_down_sync(0xffffffffu, s, o);
        if (lane == 0) out[node] = tanhf(s * (1.0f / 128.0f));
    }
}

// ================= launch =================
extern "C" void kernel_launch(void* const* d_in, const int* in_sizes, int n_in,
                              void* d_out, int out_size) {
    int ix = 0, ie = 1, iw = 2, iwih = 3, iwhh = 4, ibih = 5, ibhh = 6;
    {
        int w_seen = 0, b_seen = 0;
        for (int i = 0; i < n_in; i++) {
            long long s = in_sizes[i];
            if (s == (long long)NN * C) ix = i;
            else if (s == 2LL * NE) ie = i;
            else if (s == (long long)C3 * C) {
                if (w_seen == 0) iw = i;
                else if (w_seen == 1) iwih = i;
                else if (w_seen == 2) iwhh = i;
                w_seen++;
            } else if (s == C3) {
                if (b_seen == 0) ibih = i;
                else if (b_seen == 1) ibhh = i;
                b_seen++;
            }
        }
    }
    const float* x      = (const float*)d_in[ix];
    const void*  ei     = d_in[ie];
    const float* weight = (const float*)d_in[iw];
    const float* w_ih   = (const float*)d_in[iwih];
    const float* w_hh   = (const float*)d_in[iwhh];
    const float* b_ih   = (const float*)d_in[ibih];
    const float* b_hh   = (const float*)d_in[ibhh];
    float*       out    = (float*)d_out;

    static bool attr_set = false;
    if (!attr_set) {
        cudaFuncSetAttribute(fused_kernel, cudaFuncAttributeMaxDynamicSharedMemorySize, FUSED_SMEM);
        attr_set = true;
    }

    zero_deg_kernel<<<(NN + 255) / 256, 256>>>();
    prep1_kernel<<<NB_COUNT + NB_INIT + NB_WF, 256>>>(ei, x, weight, w_ih);
    scanA_kernel<<<SCAN_NB, SCAN_B>>>();
    scanB_kernel<<<1, 32>>>();
    scanC_kernel<<<SCAN_NB, SCAN_B>>>();
    prep2_kernel<<<NB_FILL + NB_PREPB, 256>>>(ei, w_hh);

    int gather_blocks = (NN * 32 + 255) / 256;
    int fused_blocks = (NN + NROW - 1) / NROW;   // 1563

    for (int l = 0; l < NLAYERS; l++) {
        gather_kernel<<<gather_blocks, 256>>>();
        fused_kernel<<<fused_blocks, 256, FUSED_SMEM>>>(l, b_ih, b_hh);
    }

    mean_tanh_kernel<<<(NN * 32 + 255) / 256, 256>>>(out);
}